// round 3
// baseline (speedup 1.0000x reference)
#include <cuda_runtime.h>
#include <math.h>

// Problem constants
#define Bq   512
#define NPGc 50
#define EPGc 60
#define Dd   128
#define Vv   100000
#define NSPLITS 4
#define NSCALE 12.0f
#define NN   (Bq*NPGc)   // 25600 nodes
#define EE   (Bq*EPGc)   // 30720 edges

// ---------------- scratch (device globals; no allocation allowed) ----------
__device__ float g_feat[NN*Dd];
__device__ float g_aggx[NN*Dd];   // also num1 / neigh1
__device__ float g_aggh[NN*Dd];   // also num2 / neigh2
__device__ float g_aggrh[NN*Dd];
__device__ float g_den1[NN];
__device__ float g_den2[NN];
__device__ float g_hn[NN*2*Dd];
__device__ float g_gi[NN*3*Dd];
__device__ float g_gh[NN*3*Dd];
__device__ float g_x[NN*Dd];
__device__ float g_h[NN*Dd];
__device__ float g_t1[NN*Dd];
__device__ float g_t2[NN*Dd];
__device__ float g_rr[NN*Dd];
__device__ float g_zz[NN*Dd];
__device__ float g_uu[NN*Dd];
__device__ float g_deg[NN];
__device__ float g_dis[NN];
__device__ float g_emf[EE];
__device__ float g_tend[1];
__device__ float g_sc[Vv];
__device__ float g_q[Bq*Dd];
__device__ float g_cc[Bq*2*Dd];
__device__ float g_sr[Bq*Dd];
__device__ float g_lse[Bq];

// ---------------- helpers --------------------------------------------------
__global__ void k_zero(float* p, int n){
    int i = blockIdx.x*256 + threadIdx.x;
    if (i < n) p[i] = 0.f;
}

__global__ void k_copy(const float* __restrict__ in, float* __restrict__ out, int n){
    int i = blockIdx.x*256 + threadIdx.x;
    if (i < n) out[i] = in[i];
}

// l2-normalize gathered embedding rows: feat[n] = emb[iid[n]] / max(||.||,1e-12)
__global__ void k_gather_norm(const float* __restrict__ emb, const int* __restrict__ iid,
                              float* __restrict__ out){
    int n = blockIdx.x, d = threadIdx.x;
    float v = emb[(size_t)iid[n]*Dd + d];
    float s = v*v;
    #pragma unroll
    for (int o = 16; o; o >>= 1) s += __shfl_xor_sync(0xffffffffu, s, o);
    __shared__ float sh[4];
    if ((d & 31) == 0) sh[d>>5] = s;
    __syncthreads();
    float tot = sh[0]+sh[1]+sh[2]+sh[3];
    out[(size_t)n*Dd + d] = v / fmaxf(sqrtf(tot), 1e-12f);
}

// l2-normalize rows in place (in may == out)
__global__ void k_row_norm(const float* __restrict__ in, float* __restrict__ out){
    int n = blockIdx.x, d = threadIdx.x;
    float v = in[(size_t)n*Dd + d];
    float s = v*v;
    #pragma unroll
    for (int o = 16; o; o >>= 1) s += __shfl_xor_sync(0xffffffffu, s, o);
    __shared__ float sh[4];
    if ((d & 31) == 0) sh[d>>5] = s;
    __syncthreads();
    float tot = sh[0]+sh[1]+sh[2]+sh[3];
    out[(size_t)n*Dd + d] = v / fmaxf(sqrtf(tot), 1e-12f);
}

// sc[v] = SCALE / max(||emb[v]||, 1e-12)  (folds target l2norm + logit scale)
__global__ void k_emb_scale(const float* __restrict__ emb, float* __restrict__ sc){
    int v = blockIdx.x, d = threadIdx.x;
    float x = emb[(size_t)v*Dd + d];
    float s = x*x;
    #pragma unroll
    for (int o = 16; o; o >>= 1) s += __shfl_xor_sync(0xffffffffu, s, o);
    __shared__ float sh[4];
    if ((d & 31) == 0) sh[d>>5] = s;
    __syncthreads();
    if (d == 0){
        float tot = sh[0]+sh[1]+sh[2]+sh[3];
        sc[v] = NSCALE / fmaxf(sqrtf(tot), 1e-12f);
    }
}

// weighted-degree denominators
__global__ void k_den(const int* __restrict__ src, const int* __restrict__ dst,
                      const float* __restrict__ w, float* den1, float* den2){
    int e = blockIdx.x*256 + threadIdx.x;
    if (e >= EE) return;
    float ww = w[e];
    atomicAdd(&den1[dst[e]], ww);
    atomicAdd(&den2[src[e]], ww);
}

// weighted neighbor segment sums (both directions)
__global__ void k_segnum(const int* __restrict__ src, const int* __restrict__ dst,
                         const float* __restrict__ w, const float* __restrict__ feat,
                         float* num1, float* num2){
    int e = blockIdx.x, d = threadIdx.x;
    int s = src[e], t = dst[e];
    float ww = w[e];
    atomicAdd(&num1[(size_t)t*Dd + d], feat[(size_t)s*Dd + d]*ww);
    atomicAdd(&num2[(size_t)s*Dd + d], feat[(size_t)t*Dd + d]*ww);
}

__global__ void k_div(float* num, const float* __restrict__ den, int n){
    int i = blockIdx.x*256 + threadIdx.x;
    if (i >= n) return;
    float dn = den[i/Dd];
    num[i] = num[i] / ((dn == 0.f) ? 1.f : dn);
}

// ---------------- GEMM: C[n,m] = sum_k A[n,k]*B(k,m)  (+bias / *colscale) ---
// 128x128 tile, BK=16, 256 threads, 8x8 microtile, fp32.
__global__ __launch_bounds__(256)
void k_gemm(const float* __restrict__ A, int lda,
            const float* __restrict__ Bm, int ldb, int transB,
            const float* __restrict__ bias,
            const float* __restrict__ colscale,
            float* __restrict__ C, int ldc,
            int Nr, int Mc, int K)
{
    __shared__ float As[16][132];
    __shared__ float Bs[16][132];
    int brow = blockIdx.x*128;
    int bcol = blockIdx.y*128;
    int tid = threadIdx.x;
    int tx = tid & 15, ty = tid >> 4;
    float acc[8][8];
    #pragma unroll
    for (int i = 0; i < 8; i++)
        #pragma unroll
        for (int j = 0; j < 8; j++) acc[i][j] = 0.f;

    for (int k0 = 0; k0 < K; k0 += 16){
        #pragma unroll
        for (int l = 0; l < 8; l++){
            int i = tid + l*256;
            int r = i >> 4, c = i & 15;
            int gr = brow + r;
            As[c][r] = (gr < Nr) ? A[(size_t)gr*lda + k0 + c] : 0.f;
        }
        if (transB){
            #pragma unroll
            for (int l = 0; l < 8; l++){
                int i = tid + l*256;
                int r = i >> 4, c = i & 15;         // r: m, c: k
                int gm = bcol + r;
                Bs[c][r] = (gm < Mc) ? Bm[(size_t)gm*ldb + k0 + c] : 0.f;
            }
        } else {
            #pragma unroll
            for (int l = 0; l < 8; l++){
                int i = tid + l*256;
                int r = i >> 7, c = i & 127;        // r: k, c: m
                int gm = bcol + c;
                Bs[r][c] = (gm < Mc) ? Bm[(size_t)(k0+r)*ldb + gm] : 0.f;
            }
        }
        __syncthreads();
        #pragma unroll
        for (int kk = 0; kk < 16; kk++){
            float a[8], b[8];
            #pragma unroll
            for (int i = 0; i < 8; i++) a[i] = As[kk][ty*8 + i];
            #pragma unroll
            for (int j = 0; j < 8; j++) b[j] = Bs[kk][tx*8 + j];
            #pragma unroll
            for (int i = 0; i < 8; i++)
                #pragma unroll
                for (int j = 0; j < 8; j++) acc[i][j] += a[i]*b[j];
        }
        __syncthreads();
    }
    #pragma unroll
    for (int i = 0; i < 8; i++){
        int gr = brow + ty*8 + i;
        if (gr >= Nr) continue;
        #pragma unroll
        for (int j = 0; j < 8; j++){
            int gm = bcol + tx*8 + j;
            if (gm >= Mc) continue;
            float v = acc[i][j];
            if (colscale) v *= colscale[gm];
            if (bias) v += bias[gm];
            C[(size_t)gr*ldc + gm] = v;
        }
    }
}

// ---------------- GRU update ------------------------------------------------
__global__ void k_gru(const float* __restrict__ gi, const float* __restrict__ gh,
                      float* __restrict__ feat){
    int i = blockIdx.x*256 + threadIdx.x;
    if (i >= NN*Dd) return;
    int n = i / Dd, d = i % Dd;
    size_t base = (size_t)n*3*Dd + d;
    float ir = gi[base], iz = gi[base + Dd], ig = gi[base + 2*Dd];
    float hr = gh[base], hz = gh[base + Dd], hg = gh[base + 2*Dd];
    float r = 1.f/(1.f + expf(-(ir + hr)));
    float z = 1.f/(1.f + expf(-(iz + hz)));
    float g = tanhf(ig + r*hg);
    feat[i] = (1.f - z)*g + z*feat[i];
}

// ---------------- ODE machinery --------------------------------------------
__global__ void k_tmax(const float* __restrict__ et, float* tend){
    int i = blockIdx.x*256 + threadIdx.x;
    float v = (i < EE) ? et[i] : 0.f;
    #pragma unroll
    for (int o = 16; o; o >>= 1) v = fmaxf(v, __shfl_xor_sync(0xffffffffu, v, o));
    if ((threadIdx.x & 31) == 0) atomicMax((int*)tend, __float_as_int(v)); // positive floats
}

__global__ void k_mask(const float* __restrict__ edge_t, const float* __restrict__ node_t,
                       const int* __restrict__ src, const int* __restrict__ dst,
                       const float* __restrict__ tend, int kstep,
                       float* __restrict__ emf, float* deg){
    int e = blockIdx.x*256 + threadIdx.x;
    if (e >= EE) return;
    float dt = tend[0] / (float)NSPLITS;
    float t = (float)kstep * dt;
    int s = src[e], d = dst[e];
    float m = (edge_t[e] <= t && node_t[s] >= t && node_t[d] >= t && s != d) ? 1.f : 0.f;
    emf[e] = m;
    if (m > 0.f){ atomicAdd(&deg[s], 1.f); atomicAdd(&deg[d], 1.f); }
}

__global__ void k_dis(const float* __restrict__ deg, float* __restrict__ dis){
    int n = blockIdx.x*256 + threadIdx.x;
    if (n < NN) dis[n] = 1.f / sqrtf(fmaxf(deg[n], 1.f));
}

// agg[dst] += inp[src]*dis[src]; agg[src] += inp[dst]*dis[dst]  (masked edges)
__global__ void k_agg(const int* __restrict__ src, const int* __restrict__ dst,
                      const float* __restrict__ emf, const float* __restrict__ dis,
                      const float* __restrict__ inp, float* agg){
    int e = blockIdx.x, d = threadIdx.x;
    if (emf[e] == 0.f) return;
    int s = src[e], t = dst[e];
    atomicAdd(&agg[(size_t)t*Dd + d], inp[(size_t)s*Dd + d]*dis[s]);
    atomicAdd(&agg[(size_t)s*Dd + d], inp[(size_t)t*Dd + d]*dis[t]);
}

__global__ void k_scale_dis(float* a, const float* __restrict__ dis, int n){
    int i = blockIdx.x*256 + threadIdx.x;
    if (i < n) a[i] *= dis[i/Dd];
}

__global__ void k_sigadd(const float* __restrict__ a, const float* __restrict__ b,
                         float* __restrict__ o, int n){
    int i = blockIdx.x*256 + threadIdx.x;
    if (i < n) o[i] = 1.f/(1.f + expf(-(a[i] + b[i])));
}

__global__ void k_tanhadd(const float* __restrict__ a, const float* __restrict__ b,
                          float* __restrict__ o, int n){
    int i = blockIdx.x*256 + threadIdx.x;
    if (i < n) o[i] = tanhf(a[i] + b[i]);
}

__global__ void k_mul(const float* __restrict__ a, const float* __restrict__ b,
                      float* __restrict__ o, int n){
    int i = blockIdx.x*256 + threadIdx.x;
    if (i < n) o[i] = a[i]*b[i];
}

__global__ void k_ode_update(float* __restrict__ h, const float* __restrict__ zz,
                             const float* __restrict__ uu, const float* __restrict__ node_t,
                             const float* __restrict__ tend, int kstep){
    int i = blockIdx.x*256 + threadIdx.x;
    if (i >= NN*Dd) return;
    int n = i / Dd;
    float dt = tend[0] / (float)NSPLITS;
    float t = (float)kstep * dt;
    float hv = h[i];
    float dh = (node_t[n] >= t) ? (1.f - zz[i])*(uu[i] - hv) : 0.f;
    h[i] = hv + dt*dh;
}

// ---------------- attention readout ----------------------------------------
__global__ void k_attn(const float* __restrict__ feat, const float* __restrict__ q,
                       const float* __restrict__ fwu, const float* __restrict__ We,
                       float* __restrict__ cc){
    int b = blockIdx.x, d = threadIdx.x;       // 128 threads
    __shared__ float e_sh[NPGc];
    __shared__ float red[4];
    const float* fb  = feat + (size_t)b*NPGc*Dd;
    const float* fwb = fwu  + (size_t)b*NPGc*Dd;
    float qd = q[(size_t)b*Dd + d];
    float wed = We[d];
    for (int i = 0; i < NPGc; i++){
        float s = (1.f/(1.f + expf(-(fwb[(size_t)i*Dd + d] + qd)))) * wed;
        #pragma unroll
        for (int o = 16; o; o >>= 1) s += __shfl_xor_sync(0xffffffffu, s, o);
        if ((d & 31) == 0) red[d>>5] = s;
        __syncthreads();
        if (d == 0) e_sh[i] = red[0]+red[1]+red[2]+red[3];
        __syncthreads();
    }
    float mx = -1e30f;
    for (int i = 0; i < NPGc; i++) mx = fmaxf(mx, e_sh[i]);
    float sm = 0.f;
    for (int i = 0; i < NPGc; i++) sm += expf(e_sh[i] - mx);
    float srg = 0.f;
    for (int i = 0; i < NPGc; i++) srg += fb[(size_t)i*Dd + d]*(expf(e_sh[i] - mx)/sm);
    cc[(size_t)b*2*Dd + d]      = fb[(size_t)(NPGc-1)*Dd + d];  // last
    cc[(size_t)b*2*Dd + Dd + d] = srg;
}

// ---------------- log-softmax ----------------------------------------------
__global__ void k_lse(const float* __restrict__ out, float* __restrict__ lse){
    int b = blockIdx.x, t = threadIdx.x;   // 256 threads
    const float* row = out + (size_t)b*Vv;
    __shared__ float sh[256];
    float mx = -1e30f;
    for (int v = t; v < Vv; v += 256) mx = fmaxf(mx, row[v]);
    sh[t] = mx; __syncthreads();
    for (int o = 128; o; o >>= 1){ if (t < o) sh[t] = fmaxf(sh[t], sh[t+o]); __syncthreads(); }
    mx = sh[0]; __syncthreads();
    float s = 0.f;
    for (int v = t; v < Vv; v += 256) s += expf(row[v] - mx);
    sh[t] = s; __syncthreads();
    for (int o = 128; o; o >>= 1){ if (t < o) sh[t] += sh[t+o]; __syncthreads(); }
    if (t == 0) lse[b] = mx + logf(sh[0]);
}

__global__ void k_sub(float* __restrict__ out, const float* __restrict__ lse){
    int v = blockIdx.x*256 + threadIdx.x;
    int b = blockIdx.y;
    if (v < Vv) out[(size_t)b*Vv + v] -= lse[b];
}

// ---------------- host orchestration ---------------------------------------
static inline void gemm(const float* A, int lda, const float* B, int ldb, int tB,
                        const float* bias, const float* cs,
                        float* C, int ldc, int Nr, int Mc, int K){
    dim3 grid((Nr + 127)/128, (Mc + 127)/128);
    k_gemm<<<grid, 256>>>(A, lda, B, ldb, tB, bias, cs, C, ldc, Nr, Mc, K);
}

extern "C" void kernel_launch(void* const* d_in, const int* in_sizes, int n_in,
                              void* d_out, int out_size)
{
    const int*   iid    = (const int*)  d_in[0];
    const int*   src    = (const int*)  d_in[1];
    const int*   dst    = (const int*)  d_in[2];
    const float* edge_w = (const float*)d_in[3];
    const float* edge_t = (const float*)d_in[4];
    const float* node_t = (const float*)d_in[5];
    const float* emb    = (const float*)d_in[6];
    const float* W1     = (const float*)d_in[7];
    const float* W2     = (const float*)d_in[8];
    const float* gw_ih  = (const float*)d_in[9];
    const float* gw_hh  = (const float*)d_in[10];
    const float* gb_ih  = (const float*)d_in[11];
    const float* gb_hh  = (const float*)d_in[12];
    const float* Wxr = (const float*)d_in[13]; const float* bxr = (const float*)d_in[14];
    const float* Wxz = (const float*)d_in[15]; const float* bxz = (const float*)d_in[16];
    const float* Wxh = (const float*)d_in[17]; const float* bxh = (const float*)d_in[18];
    const float* Whr = (const float*)d_in[19]; const float* bhr = (const float*)d_in[20];
    const float* Whz = (const float*)d_in[21]; const float* bhz = (const float*)d_in[22];
    const float* Whh = (const float*)d_in[23]; const float* bhh = (const float*)d_in[24];
    const float* Wu  = (const float*)d_in[25];
    const float* Wv  = (const float*)d_in[26];
    const float* bv  = (const float*)d_in[27];
    const float* We  = (const float*)d_in[28];
    const float* W_sr= (const float*)d_in[29];
    float* out = (float*)d_out;

    float *p_feat,*p_aggx,*p_aggh,*p_aggrh,*p_den1,*p_den2,*p_hn,*p_gi,*p_gh;
    float *p_x,*p_h,*p_t1,*p_t2,*p_rr,*p_zz,*p_uu,*p_deg,*p_dis,*p_emf,*p_tend;
    float *p_sc,*p_q,*p_cc,*p_sr,*p_lse;
    cudaGetSymbolAddress((void**)&p_feat, g_feat);
    cudaGetSymbolAddress((void**)&p_aggx, g_aggx);
    cudaGetSymbolAddress((void**)&p_aggh, g_aggh);
    cudaGetSymbolAddress((void**)&p_aggrh,g_aggrh);
    cudaGetSymbolAddress((void**)&p_den1, g_den1);
    cudaGetSymbolAddress((void**)&p_den2, g_den2);
    cudaGetSymbolAddress((void**)&p_hn,   g_hn);
    cudaGetSymbolAddress((void**)&p_gi,   g_gi);
    cudaGetSymbolAddress((void**)&p_gh,   g_gh);
    cudaGetSymbolAddress((void**)&p_x,    g_x);
    cudaGetSymbolAddress((void**)&p_h,    g_h);
    cudaGetSymbolAddress((void**)&p_t1,   g_t1);
    cudaGetSymbolAddress((void**)&p_t2,   g_t2);
    cudaGetSymbolAddress((void**)&p_rr,   g_rr);
    cudaGetSymbolAddress((void**)&p_zz,   g_zz);
    cudaGetSymbolAddress((void**)&p_uu,   g_uu);
    cudaGetSymbolAddress((void**)&p_deg,  g_deg);
    cudaGetSymbolAddress((void**)&p_dis,  g_dis);
    cudaGetSymbolAddress((void**)&p_emf,  g_emf);
    cudaGetSymbolAddress((void**)&p_tend, g_tend);
    cudaGetSymbolAddress((void**)&p_sc,   g_sc);
    cudaGetSymbolAddress((void**)&p_q,    g_q);
    cudaGetSymbolAddress((void**)&p_cc,   g_cc);
    cudaGetSymbolAddress((void**)&p_sr,   g_sr);
    cudaGetSymbolAddress((void**)&p_lse,  g_lse);

    const int ND = NN*Dd;
    #define ZERO(p, n) k_zero<<<((n)+255)/256, 256>>>(p, (int)(n))

    // ---- Stage A: feat = l2norm(emb[iid]); target scales ----
    k_gather_norm<<<NN, 128>>>(emb, iid, p_feat);
    k_emb_scale<<<Vv, 128>>>(emb, p_sc);

    // ---- Stage B: weighted neighbor means ----
    ZERO(p_aggx, ND); ZERO(p_aggh, ND); ZERO(p_den1, NN); ZERO(p_den2, NN);
    k_den<<<(EE+255)/256, 256>>>(src, dst, edge_w, p_den1, p_den2);
    k_segnum<<<EE, 128>>>(src, dst, edge_w, p_feat, p_aggx, p_aggh);
    k_div<<<(ND+255)/256, 256>>>(p_aggx, p_den1, ND);
    k_div<<<(ND+255)/256, 256>>>(p_aggh, p_den2, ND);

    // ---- Stage C: hn, gi, gh ----
    gemm(p_aggx, Dd, W1, Dd, 0, nullptr, nullptr, p_hn,        2*Dd, NN, Dd, Dd);
    gemm(p_aggh, Dd, W2, Dd, 0, nullptr, nullptr, p_hn + Dd,   2*Dd, NN, Dd, Dd);
    gemm(p_hn, 2*Dd, gw_ih, 2*Dd, 1, gb_ih, nullptr, p_gi, 3*Dd, NN, 3*Dd, 2*Dd);
    gemm(p_feat,  Dd, gw_hh,   Dd, 1, gb_hh, nullptr, p_gh, 3*Dd, NN, 3*Dd, Dd);

    // ---- Stage D: GRU + norm ----
    k_gru<<<(ND+255)/256, 256>>>(p_gi, p_gh, p_feat);
    k_row_norm<<<NN, 128>>>(p_feat, p_feat);

    // ---- Stage E: ODE ----
    k_copy<<<(ND+255)/256, 256>>>(p_feat, p_x, ND);
    k_copy<<<(ND+255)/256, 256>>>(p_feat, p_h, ND);
    ZERO(p_tend, 1);
    k_tmax<<<(EE+255)/256, 256>>>(edge_t, p_tend);

    for (int k = 0; k < NSPLITS; k++){
        ZERO(p_deg, NN); ZERO(p_aggx, ND); ZERO(p_aggh, ND); ZERO(p_aggrh, ND);
        k_mask<<<(EE+255)/256, 256>>>(edge_t, node_t, src, dst, p_tend, k, p_emf, p_deg);
        k_dis<<<(NN+255)/256, 256>>>(p_deg, p_dis);
        k_agg<<<EE, 128>>>(src, dst, p_emf, p_dis, p_x, p_aggx);
        k_agg<<<EE, 128>>>(src, dst, p_emf, p_dis, p_h, p_aggh);
        k_scale_dis<<<(ND+255)/256, 256>>>(p_aggx, p_dis, ND);
        k_scale_dis<<<(ND+255)/256, 256>>>(p_aggh, p_dis, ND);
        // rr
        gemm(p_aggx, Dd, Wxr, Dd, 0, bxr, nullptr, p_t1, Dd, NN, Dd, Dd);
        gemm(p_aggh, Dd, Whr, Dd, 0, bhr, nullptr, p_t2, Dd, NN, Dd, Dd);
        k_sigadd<<<(ND+255)/256, 256>>>(p_t1, p_t2, p_rr, ND);
        // zz
        gemm(p_aggx, Dd, Wxz, Dd, 0, bxz, nullptr, p_t1, Dd, NN, Dd, Dd);
        gemm(p_aggh, Dd, Whz, Dd, 0, bhz, nullptr, p_t2, Dd, NN, Dd, Dd);
        k_sigadd<<<(ND+255)/256, 256>>>(p_t1, p_t2, p_zz, ND);
        // uu
        k_mul<<<(ND+255)/256, 256>>>(p_rr, p_h, p_uu, ND);  // rh in p_uu
        k_agg<<<EE, 128>>>(src, dst, p_emf, p_dis, p_uu, p_aggrh);
        k_scale_dis<<<(ND+255)/256, 256>>>(p_aggrh, p_dis, ND);
        gemm(p_aggx,  Dd, Wxh, Dd, 0, bxh, nullptr, p_t1, Dd, NN, Dd, Dd);
        gemm(p_aggrh, Dd, Whh, Dd, 0, bhh, nullptr, p_t2, Dd, NN, Dd, Dd);
        k_tanhadd<<<(ND+255)/256, 256>>>(p_t1, p_t2, p_uu, ND);
        // h += dt * masked((1-zz)*(uu-h))
        k_ode_update<<<(ND+255)/256, 256>>>(p_h, p_zz, p_uu, node_t, p_tend, k);
    }
    k_row_norm<<<NN, 128>>>(p_h, p_feat);

    // ---- Stage F: attention readout ----
    gemm(p_feat, Dd, Wu, Dd, 0, nullptr, nullptr, p_t1, Dd, NN, Dd, Dd);         // fb@Wu
    gemm(p_feat + (NPGc-1)*Dd, NPGc*Dd, Wv, Dd, 0, bv, nullptr, p_q, Dd, Bq, Dd, Dd); // last@Wv+bv
    k_attn<<<Bq, 128>>>(p_feat, p_q, p_t1, We, p_cc);
    gemm(p_cc, 2*Dd, W_sr, Dd, 0, nullptr, nullptr, p_sr, Dd, Bq, Dd, 2*Dd);
    k_row_norm<<<Bq, 128>>>(p_sr, p_sr);

    // ---- Stage G: logits + log_softmax ----
    gemm(p_sr, Dd, emb, Dd, 1, nullptr, p_sc, out, Vv, Bq, Vv, Dd);
    k_lse<<<Bq, 256>>>(out, p_lse);
    k_sub<<<dim3((Vv+255)/256, Bq), 256>>>(out, p_lse);

    #undef ZERO
}

// round 5
// speedup vs baseline: 1.8765x; 1.8765x over previous
#include <cuda_runtime.h>
#include <math.h>
#include <stdint.h>

// Problem constants
#define Bq   512
#define NPGc 50
#define EPGc 60
#define Dd   128
#define Vv   100000
#define NSPLITS 4
#define NSCALE 12.0f
#define NN   (Bq*NPGc)   // 25600 nodes
#define EE   (Bq*EPGc)   // 30720 edges

// ---------------- scratch (device globals; no allocation allowed) ----------
__device__ float g_feat[NN*Dd];
__device__ float g_aggx[NN*Dd];   // also num1 / neigh1
__device__ float g_aggh[NN*Dd];   // also num2 / neigh2
__device__ float g_aggrh[NN*Dd];
__device__ float g_den1[NN];
__device__ float g_den2[NN];
__device__ float g_hn[NN*2*Dd];
__device__ float g_gi[NN*3*Dd];
__device__ float g_gh[NN*3*Dd];
__device__ float g_x[NN*Dd];
__device__ float g_h[NN*Dd];
__device__ float g_t1[NN*Dd];
__device__ float g_t2[NN*Dd];
__device__ float g_rr[NN*Dd];
__device__ float g_zz[NN*Dd];
__device__ float g_uu[NN*Dd];
__device__ float g_deg[NN];
__device__ float g_dis[NN];
__device__ float g_emf[EE];
__device__ float g_tend[1];
__device__ float g_sc[Vv];
__device__ float g_q[Bq*Dd];
__device__ float g_cc[Bq*2*Dd];
__device__ float g_sr[Bq*Dd];
__device__ float g_lse[Bq];

// ---------------- helpers --------------------------------------------------
__global__ void k_zero(float* p, int n){
    int i = blockIdx.x*256 + threadIdx.x;
    if (i < n) p[i] = 0.f;
}

__global__ void k_copy(const float* __restrict__ in, float* __restrict__ out, int n){
    int i = blockIdx.x*256 + threadIdx.x;
    if (i < n) out[i] = in[i];
}

// l2-normalize gathered embedding rows: feat[n] = emb[iid[n]] / max(||.||,1e-12)
__global__ void k_gather_norm(const float* __restrict__ emb, const int* __restrict__ iid,
                              float* __restrict__ out){
    int n = blockIdx.x, d = threadIdx.x;
    float v = emb[(size_t)iid[n]*Dd + d];
    float s = v*v;
    #pragma unroll
    for (int o = 16; o; o >>= 1) s += __shfl_xor_sync(0xffffffffu, s, o);
    __shared__ float sh[4];
    if ((d & 31) == 0) sh[d>>5] = s;
    __syncthreads();
    float tot = sh[0]+sh[1]+sh[2]+sh[3];
    out[(size_t)n*Dd + d] = v / fmaxf(sqrtf(tot), 1e-12f);
}

// l2-normalize rows (in may == out)
__global__ void k_row_norm(const float* __restrict__ in, float* __restrict__ out){
    int n = blockIdx.x, d = threadIdx.x;
    float v = in[(size_t)n*Dd + d];
    float s = v*v;
    #pragma unroll
    for (int o = 16; o; o >>= 1) s += __shfl_xor_sync(0xffffffffu, s, o);
    __shared__ float sh[4];
    if ((d & 31) == 0) sh[d>>5] = s;
    __syncthreads();
    float tot = sh[0]+sh[1]+sh[2]+sh[3];
    out[(size_t)n*Dd + d] = v / fmaxf(sqrtf(tot), 1e-12f);
}

// sc[v] = SCALE / max(||emb[v]||, 1e-12)
__global__ void k_emb_scale(const float* __restrict__ emb, float* __restrict__ sc){
    int v = blockIdx.x, d = threadIdx.x;
    float x = emb[(size_t)v*Dd + d];
    float s = x*x;
    #pragma unroll
    for (int o = 16; o; o >>= 1) s += __shfl_xor_sync(0xffffffffu, s, o);
    __shared__ float sh[4];
    if ((d & 31) == 0) sh[d>>5] = s;
    __syncthreads();
    if (d == 0){
        float tot = sh[0]+sh[1]+sh[2]+sh[3];
        sc[v] = NSCALE / fmaxf(sqrtf(tot), 1e-12f);
    }
}

// weighted-degree denominators
__global__ void k_den(const int* __restrict__ src, const int* __restrict__ dst,
                      const float* __restrict__ w, float* den1, float* den2){
    int e = blockIdx.x*256 + threadIdx.x;
    if (e >= EE) return;
    float ww = w[e];
    atomicAdd(&den1[dst[e]], ww);
    atomicAdd(&den2[src[e]], ww);
}

// turn den into rowscale: r = (den==0) ? 1 : 1/den
__global__ void k_recip(float* d, int n){
    int i = blockIdx.x*256 + threadIdx.x;
    if (i >= n) return;
    float v = d[i];
    d[i] = (v == 0.f) ? 1.f : 1.f/v;
}

// weighted neighbor segment sums (both directions)
__global__ void k_segnum(const int* __restrict__ src, const int* __restrict__ dst,
                         const float* __restrict__ w, const float* __restrict__ feat,
                         float* num1, float* num2){
    int e = blockIdx.x, d = threadIdx.x;
    int s = src[e], t = dst[e];
    float ww = w[e];
    atomicAdd(&num1[(size_t)t*Dd + d], feat[(size_t)s*Dd + d]*ww);
    atomicAdd(&num2[(size_t)s*Dd + d], feat[(size_t)t*Dd + d]*ww);
}

// ---------------- TF32 tensor-core GEMM ------------------------------------
// C[n,m] = sum_k (A[n,k]*rowscale[n]) * B(k,m); optional *colscale[m], +bias[m]
// 128x128 tile, BK=16, 256 threads (8 warps, 4x2), warp tile 32x64,
// mma.sync.m16n8k8.tf32 (fp32 accumulate). A,B rounded to tf32 in the smem
// staging stage (cvt.rna) so the inner loop is pure LDS + HMMA.
__global__ __launch_bounds__(256)
void k_gemm_tc(const float* __restrict__ A, int lda,
               const float* __restrict__ Bm, int ldb, int transB,
               const float* __restrict__ bias,
               const float* __restrict__ colscale,
               const float* __restrict__ rowscale,
               float* __restrict__ C, int ldc,
               int Nr, int Mc, int K)
{
    __shared__ float As[16][136];   // [k][m]  (136 stride: conflict-free frags)
    __shared__ float Bs[16][136];   // [k][n]
    int brow = blockIdx.x*128;
    int bcol = blockIdx.y*128;
    int tid  = threadIdx.x;
    int warp = tid >> 5, lane = tid & 31;
    int gid  = lane >> 2, tig = lane & 3;  // groupID, thread-in-group
    int wm   = (warp & 3) * 32;            // warp row offset (m)
    int wn   = (warp >> 2) * 64;           // warp col offset (n)

    float acc[2][8][4];
    #pragma unroll
    for (int mt = 0; mt < 2; mt++)
        #pragma unroll
        for (int nt = 0; nt < 8; nt++)
            #pragma unroll
            for (int f = 0; f < 4; f++) acc[mt][nt][f] = 0.f;

    for (int k0 = 0; k0 < K; k0 += 16){
        // stage A (with optional row scaling), tf32-round into smem
        #pragma unroll
        for (int l = 0; l < 8; l++){
            int i = tid + l*256;
            int r = i >> 4, c = i & 15;
            int gr = brow + r;
            float v = 0.f;
            if (gr < Nr){
                v = A[(size_t)gr*lda + k0 + c];
                if (rowscale) v *= rowscale[gr];
            }
            uint32_t t; asm("cvt.rna.tf32.f32 %0, %1;" : "=r"(t) : "f"(v));
            As[c][r] = __uint_as_float(t);
        }
        // stage B
        if (transB){
            #pragma unroll
            for (int l = 0; l < 8; l++){
                int i = tid + l*256;
                int r = i >> 4, c = i & 15;         // r: n-local, c: k-local
                int gm = bcol + r;
                float v = (gm < Mc) ? Bm[(size_t)gm*ldb + k0 + c] : 0.f;
                uint32_t t; asm("cvt.rna.tf32.f32 %0, %1;" : "=r"(t) : "f"(v));
                Bs[c][r] = __uint_as_float(t);
            }
        } else {
            #pragma unroll
            for (int l = 0; l < 8; l++){
                int i = tid + l*256;
                int r = i >> 7, c = i & 127;        // r: k-local, c: n-local
                int gm = bcol + c;
                float v = (gm < Mc) ? Bm[(size_t)(k0+r)*ldb + gm] : 0.f;
                uint32_t t; asm("cvt.rna.tf32.f32 %0, %1;" : "=r"(t) : "f"(v));
                Bs[r][c] = __uint_as_float(t);
            }
        }
        __syncthreads();

        #pragma unroll
        for (int ks = 0; ks < 16; ks += 8){
            uint32_t a[2][4], b[8][2];
            #pragma unroll
            for (int mt = 0; mt < 2; mt++){
                int rb = wm + mt*16;
                a[mt][0] = __float_as_uint(As[ks+tig  ][rb+gid  ]);
                a[mt][1] = __float_as_uint(As[ks+tig  ][rb+gid+8]);
                a[mt][2] = __float_as_uint(As[ks+tig+4][rb+gid  ]);
                a[mt][3] = __float_as_uint(As[ks+tig+4][rb+gid+8]);
            }
            #pragma unroll
            for (int nt = 0; nt < 8; nt++){
                int cb = wn + nt*8;
                b[nt][0] = __float_as_uint(Bs[ks+tig  ][cb+gid]);
                b[nt][1] = __float_as_uint(Bs[ks+tig+4][cb+gid]);
            }
            #pragma unroll
            for (int mt = 0; mt < 2; mt++)
                #pragma unroll
                for (int nt = 0; nt < 8; nt++)
                    asm volatile(
                        "mma.sync.aligned.m16n8k8.row.col.f32.tf32.tf32.f32 "
                        "{%0,%1,%2,%3}, {%4,%5,%6,%7}, {%8,%9}, {%0,%1,%2,%3};"
                        : "+f"(acc[mt][nt][0]), "+f"(acc[mt][nt][1]),
                          "+f"(acc[mt][nt][2]), "+f"(acc[mt][nt][3])
                        : "r"(a[mt][0]), "r"(a[mt][1]), "r"(a[mt][2]), "r"(a[mt][3]),
                          "r"(b[nt][0]), "r"(b[nt][1]));
        }
        __syncthreads();
    }

    // epilogue: c0:(gid, 2*tig) c1:(gid, 2*tig+1) c2:(gid+8, 2*tig) c3:(gid+8, 2*tig+1)
    #pragma unroll
    for (int mt = 0; mt < 2; mt++){
        #pragma unroll
        for (int half = 0; half < 2; half++){
            int r = brow + wm + mt*16 + gid + half*8;
            if (r >= Nr) continue;
            #pragma unroll
            for (int nt = 0; nt < 8; nt++){
                int c0 = bcol + wn + nt*8 + tig*2;
                #pragma unroll
                for (int jj = 0; jj < 2; jj++){
                    int cm = c0 + jj;
                    if (cm >= Mc) continue;
                    float v = acc[mt][nt][half*2 + jj];
                    if (colscale) v *= colscale[cm];
                    if (bias) v += bias[cm];
                    C[(size_t)r*ldc + cm] = v;
                }
            }
        }
    }
}

// ---------------- GRU update ------------------------------------------------
__global__ void k_gru(const float* __restrict__ gi, const float* __restrict__ gh,
                      float* __restrict__ feat){
    int i = blockIdx.x*256 + threadIdx.x;
    if (i >= NN*Dd) return;
    int n = i / Dd, d = i % Dd;
    size_t base = (size_t)n*3*Dd + d;
    float ir = gi[base], iz = gi[base + Dd], ig = gi[base + 2*Dd];
    float hr = gh[base], hz = gh[base + Dd], hg = gh[base + 2*Dd];
    float r = 1.f/(1.f + expf(-(ir + hr)));
    float z = 1.f/(1.f + expf(-(iz + hz)));
    float g = tanhf(ig + r*hg);
    feat[i] = (1.f - z)*g + z*feat[i];
}

// ---------------- ODE machinery --------------------------------------------
__global__ void k_tmax(const float* __restrict__ et, float* tend){
    int i = blockIdx.x*256 + threadIdx.x;
    float v = (i < EE) ? et[i] : 0.f;
    #pragma unroll
    for (int o = 16; o; o >>= 1) v = fmaxf(v, __shfl_xor_sync(0xffffffffu, v, o));
    if ((threadIdx.x & 31) == 0) atomicMax((int*)tend, __float_as_int(v)); // positive floats
}

__global__ void k_mask(const float* __restrict__ edge_t, const float* __restrict__ node_t,
                       const int* __restrict__ src, const int* __restrict__ dst,
                       const float* __restrict__ tend, int kstep,
                       float* __restrict__ emf, float* deg){
    int e = blockIdx.x*256 + threadIdx.x;
    if (e >= EE) return;
    float dt = tend[0] / (float)NSPLITS;
    float t = (float)kstep * dt;
    int s = src[e], d = dst[e];
    float m = (edge_t[e] <= t && node_t[s] >= t && node_t[d] >= t && s != d) ? 1.f : 0.f;
    emf[e] = m;
    if (m > 0.f){ atomicAdd(&deg[s], 1.f); atomicAdd(&deg[d], 1.f); }
}

__global__ void k_dis(const float* __restrict__ deg, float* __restrict__ dis){
    int n = blockIdx.x*256 + threadIdx.x;
    if (n < NN) dis[n] = 1.f / sqrtf(fmaxf(deg[n], 1.f));
}

// agg[dst] += inp[src]*dis[src]; agg[src] += inp[dst]*dis[dst]  (masked edges)
__global__ void k_agg(const int* __restrict__ src, const int* __restrict__ dst,
                      const float* __restrict__ emf, const float* __restrict__ dis,
                      const float* __restrict__ inp, float* agg){
    int e = blockIdx.x, d = threadIdx.x;
    if (emf[e] == 0.f) return;
    int s = src[e], t = dst[e];
    atomicAdd(&agg[(size_t)t*Dd + d], inp[(size_t)s*Dd + d]*dis[s]);
    atomicAdd(&agg[(size_t)s*Dd + d], inp[(size_t)t*Dd + d]*dis[t]);
}

__global__ void k_sigadd(const float* __restrict__ a, const float* __restrict__ b,
                         float* __restrict__ o, int n){
    int i = blockIdx.x*256 + threadIdx.x;
    if (i < n) o[i] = 1.f/(1.f + expf(-(a[i] + b[i])));
}

__global__ void k_tanhadd(const float* __restrict__ a, const float* __restrict__ b,
                          float* __restrict__ o, int n){
    int i = blockIdx.x*256 + threadIdx.x;
    if (i < n) o[i] = tanhf(a[i] + b[i]);
}

__global__ void k_mul(const float* __restrict__ a, const float* __restrict__ b,
                      float* __restrict__ o, int n){
    int i = blockIdx.x*256 + threadIdx.x;
    if (i < n) o[i] = a[i]*b[i];
}

__global__ void k_ode_update(float* __restrict__ h, const float* __restrict__ zz,
                             const float* __restrict__ uu, const float* __restrict__ node_t,
                             const float* __restrict__ tend, int kstep){
    int i = blockIdx.x*256 + threadIdx.x;
    if (i >= NN*Dd) return;
    int n = i / Dd;
    float dt = tend[0] / (float)NSPLITS;
    float t = (float)kstep * dt;
    float hv = h[i];
    float dh = (node_t[n] >= t) ? (1.f - zz[i])*(uu[i] - hv) : 0.f;
    h[i] = hv + dt*dh;
}

// ---------------- attention readout ----------------------------------------
__global__ void k_attn(const float* __restrict__ feat, const float* __restrict__ q,
                       const float* __restrict__ fwu, const float* __restrict__ We,
                       float* __restrict__ cc){
    int b = blockIdx.x, d = threadIdx.x;       // 128 threads
    __shared__ float e_sh[NPGc];
    __shared__ float red[4];
    const float* fb  = feat + (size_t)b*NPGc*Dd;
    const float* fwb = fwu  + (size_t)b*NPGc*Dd;
    float qd = q[(size_t)b*Dd + d];
    float wed = We[d];
    for (int i = 0; i < NPGc; i++){
        float s = (1.f/(1.f + expf(-(fwb[(size_t)i*Dd + d] + qd)))) * wed;
        #pragma unroll
        for (int o = 16; o; o >>= 1) s += __shfl_xor_sync(0xffffffffu, s, o);
        if ((d & 31) == 0) red[d>>5] = s;
        __syncthreads();
        if (d == 0) e_sh[i] = red[0]+red[1]+red[2]+red[3];
        __syncthreads();
    }
    float mx = -1e30f;
    for (int i = 0; i < NPGc; i++) mx = fmaxf(mx, e_sh[i]);
    float sm = 0.f;
    for (int i = 0; i < NPGc; i++) sm += expf(e_sh[i] - mx);
    float srg = 0.f;
    for (int i = 0; i < NPGc; i++) srg += fb[(size_t)i*Dd + d]*(expf(e_sh[i] - mx)/sm);
    cc[(size_t)b*2*Dd + d]      = fb[(size_t)(NPGc-1)*Dd + d];  // last
    cc[(size_t)b*2*Dd + Dd + d] = srg;
}

// ---------------- log-softmax ----------------------------------------------
__global__ void k_lse(const float* __restrict__ out, float* __restrict__ lse){
    int b = blockIdx.x, t = threadIdx.x;   // 256 threads
    const float* row = out + (size_t)b*Vv;
    __shared__ float sh[256];
    float mx = -1e30f;
    for (int v = t; v < Vv; v += 256) mx = fmaxf(mx, row[v]);
    sh[t] = mx; __syncthreads();
    for (int o = 128; o; o >>= 1){ if (t < o) sh[t] = fmaxf(sh[t], sh[t+o]); __syncthreads(); }
    mx = sh[0]; __syncthreads();
    float s = 0.f;
    for (int v = t; v < Vv; v += 256) s += expf(row[v] - mx);
    sh[t] = s; __syncthreads();
    for (int o = 128; o; o >>= 1){ if (t < o) sh[t] += sh[t+o]; __syncthreads(); }
    if (t == 0) lse[b] = mx + logf(sh[0]);
}

__global__ void k_sub(float* __restrict__ out, const float* __restrict__ lse){
    int v = blockIdx.x*256 + threadIdx.x;
    int b = blockIdx.y;
    if (v < Vv) out[(size_t)b*Vv + v] -= lse[b];
}

// ---------------- host orchestration ---------------------------------------
static inline void gemm(const float* A, int lda, const float* B, int ldb, int tB,
                        const float* bias, const float* cs, const float* rs,
                        float* C, int ldc, int Nr, int Mc, int K){
    dim3 grid((Nr + 127)/128, (Mc + 127)/128);
    k_gemm_tc<<<grid, 256>>>(A, lda, B, ldb, tB, bias, cs, rs, C, ldc, Nr, Mc, K);
}

extern "C" void kernel_launch(void* const* d_in, const int* in_sizes, int n_in,
                              void* d_out, int out_size)
{
    const int*   iid    = (const int*)  d_in[0];
    const int*   src    = (const int*)  d_in[1];
    const int*   dst    = (const int*)  d_in[2];
    const float* edge_w = (const float*)d_in[3];
    const float* edge_t = (const float*)d_in[4];
    const float* node_t = (const float*)d_in[5];
    const float* emb    = (const float*)d_in[6];
    const float* W1     = (const float*)d_in[7];
    const float* W2     = (const float*)d_in[8];
    const float* gw_ih  = (const float*)d_in[9];
    const float* gw_hh  = (const float*)d_in[10];
    const float* gb_ih  = (const float*)d_in[11];
    const float* gb_hh  = (const float*)d_in[12];
    const float* Wxr = (const float*)d_in[13]; const float* bxr = (const float*)d_in[14];
    const float* Wxz = (const float*)d_in[15]; const float* bxz = (const float*)d_in[16];
    const float* Wxh = (const float*)d_in[17]; const float* bxh = (const float*)d_in[18];
    const float* Whr = (const float*)d_in[19]; const float* bhr = (const float*)d_in[20];
    const float* Whz = (const float*)d_in[21]; const float* bhz = (const float*)d_in[22];
    const float* Whh = (const float*)d_in[23]; const float* bhh = (const float*)d_in[24];
    const float* Wu  = (const float*)d_in[25];
    const float* Wv  = (const float*)d_in[26];
    const float* bv  = (const float*)d_in[27];
    const float* We  = (const float*)d_in[28];
    const float* W_sr= (const float*)d_in[29];
    float* out = (float*)d_out;

    float *p_feat,*p_aggx,*p_aggh,*p_aggrh,*p_den1,*p_den2,*p_hn,*p_gi,*p_gh;
    float *p_x,*p_h,*p_t1,*p_t2,*p_rr,*p_zz,*p_uu,*p_deg,*p_dis,*p_emf,*p_tend;
    float *p_sc,*p_q,*p_cc,*p_sr,*p_lse;
    cudaGetSymbolAddress((void**)&p_feat, g_feat);
    cudaGetSymbolAddress((void**)&p_aggx, g_aggx);
    cudaGetSymbolAddress((void**)&p_aggh, g_aggh);
    cudaGetSymbolAddress((void**)&p_aggrh,g_aggrh);
    cudaGetSymbolAddress((void**)&p_den1, g_den1);
    cudaGetSymbolAddress((void**)&p_den2, g_den2);
    cudaGetSymbolAddress((void**)&p_hn,   g_hn);
    cudaGetSymbolAddress((void**)&p_gi,   g_gi);
    cudaGetSymbolAddress((void**)&p_gh,   g_gh);
    cudaGetSymbolAddress((void**)&p_x,    g_x);
    cudaGetSymbolAddress((void**)&p_h,    g_h);
    cudaGetSymbolAddress((void**)&p_t1,   g_t1);
    cudaGetSymbolAddress((void**)&p_t2,   g_t2);
    cudaGetSymbolAddress((void**)&p_rr,   g_rr);
    cudaGetSymbolAddress((void**)&p_zz,   g_zz);
    cudaGetSymbolAddress((void**)&p_uu,   g_uu);
    cudaGetSymbolAddress((void**)&p_deg,  g_deg);
    cudaGetSymbolAddress((void**)&p_dis,  g_dis);
    cudaGetSymbolAddress((void**)&p_emf,  g_emf);
    cudaGetSymbolAddress((void**)&p_tend, g_tend);
    cudaGetSymbolAddress((void**)&p_sc,   g_sc);
    cudaGetSymbolAddress((void**)&p_q,    g_q);
    cudaGetSymbolAddress((void**)&p_cc,   g_cc);
    cudaGetSymbolAddress((void**)&p_sr,   g_sr);
    cudaGetSymbolAddress((void**)&p_lse,  g_lse);

    const int ND = NN*Dd;
    #define ZERO(p, n) k_zero<<<((n)+255)/256, 256>>>(p, (int)(n))

    // ---- Stage A: feat = l2norm(emb[iid]); target scales ----
    k_gather_norm<<<NN, 128>>>(emb, iid, p_feat);
    k_emb_scale<<<Vv, 128>>>(emb, p_sc);

    // ---- Stage B: weighted neighbor sums (division folded into GEMM rowscale) ----
    ZERO(p_aggx, ND); ZERO(p_aggh, ND); ZERO(p_den1, NN); ZERO(p_den2, NN);
    k_den<<<(EE+255)/256, 256>>>(src, dst, edge_w, p_den1, p_den2);
    k_segnum<<<EE, 128>>>(src, dst, edge_w, p_feat, p_aggx, p_aggh);
    k_recip<<<(NN+255)/256, 256>>>(p_den1, NN);
    k_recip<<<(NN+255)/256, 256>>>(p_den2, NN);

    // ---- Stage C: hn, gi, gh ----
    gemm(p_aggx, Dd, W1, Dd, 0, nullptr, nullptr, p_den1, p_hn,      2*Dd, NN, Dd, Dd);
    gemm(p_aggh, Dd, W2, Dd, 0, nullptr, nullptr, p_den2, p_hn + Dd, 2*Dd, NN, Dd, Dd);
    gemm(p_hn, 2*Dd, gw_ih, 2*Dd, 1, gb_ih, nullptr, nullptr, p_gi, 3*Dd, NN, 3*Dd, 2*Dd);
    gemm(p_feat,  Dd, gw_hh,   Dd, 1, gb_hh, nullptr, nullptr, p_gh, 3*Dd, NN, 3*Dd, Dd);

    // ---- Stage D: GRU + norm ----
    k_gru<<<(ND+255)/256, 256>>>(p_gi, p_gh, p_feat);
    k_row_norm<<<NN, 128>>>(p_feat, p_feat);

    // ---- Stage E: ODE ----
    k_copy<<<(ND+255)/256, 256>>>(p_feat, p_x, ND);
    k_copy<<<(ND+255)/256, 256>>>(p_feat, p_h, ND);
    ZERO(p_tend, 1);
    k_tmax<<<(EE+255)/256, 256>>>(edge_t, p_tend);

    for (int k = 0; k < NSPLITS; k++){
        ZERO(p_deg, NN); ZERO(p_aggx, ND); ZERO(p_aggh, ND); ZERO(p_aggrh, ND);
        k_mask<<<(EE+255)/256, 256>>>(edge_t, node_t, src, dst, p_tend, k, p_emf, p_deg);
        k_dis<<<(NN+255)/256, 256>>>(p_deg, p_dis);
        k_agg<<<EE, 128>>>(src, dst, p_emf, p_dis, p_x, p_aggx);
        k_agg<<<EE, 128>>>(src, dst, p_emf, p_dis, p_h, p_aggh);
        // post-agg dis scaling folded into GEMM rowscale (= p_dis)
        // rr
        gemm(p_aggx, Dd, Wxr, Dd, 0, bxr, nullptr, p_dis, p_t1, Dd, NN, Dd, Dd);
        gemm(p_aggh, Dd, Whr, Dd, 0, bhr, nullptr, p_dis, p_t2, Dd, NN, Dd, Dd);
        k_sigadd<<<(ND+255)/256, 256>>>(p_t1, p_t2, p_rr, ND);
        // zz
        gemm(p_aggx, Dd, Wxz, Dd, 0, bxz, nullptr, p_dis, p_t1, Dd, NN, Dd, Dd);
        gemm(p_aggh, Dd, Whz, Dd, 0, bhz, nullptr, p_dis, p_t2, Dd, NN, Dd, Dd);
        k_sigadd<<<(ND+255)/256, 256>>>(p_t1, p_t2, p_zz, ND);
        // uu
        k_mul<<<(ND+255)/256, 256>>>(p_rr, p_h, p_uu, ND);  // rh in p_uu
        k_agg<<<EE, 128>>>(src, dst, p_emf, p_dis, p_uu, p_aggrh);
        gemm(p_aggx,  Dd, Wxh, Dd, 0, bxh, nullptr, p_dis, p_t1, Dd, NN, Dd, Dd);
        gemm(p_aggrh, Dd, Whh, Dd, 0, bhh, nullptr, p_dis, p_t2, Dd, NN, Dd, Dd);
        k_tanhadd<<<(ND+255)/256, 256>>>(p_t1, p_t2, p_uu, ND);
        // h += dt * masked((1-zz)*(uu-h))
        k_ode_update<<<(ND+255)/256, 256>>>(p_h, p_zz, p_uu, node_t, p_tend, k);
    }
    k_row_norm<<<NN, 128>>>(p_h, p_feat);

    // ---- Stage F: attention readout ----
    gemm(p_feat, Dd, Wu, Dd, 0, nullptr, nullptr, nullptr, p_t1, Dd, NN, Dd, Dd);      // fb@Wu
    gemm(p_feat + (NPGc-1)*Dd, NPGc*Dd, Wv, Dd, 0, bv, nullptr, nullptr, p_q, Dd, Bq, Dd, Dd);
    k_attn<<<Bq, 128>>>(p_feat, p_q, p_t1, We, p_cc);
    gemm(p_cc, 2*Dd, W_sr, Dd, 0, nullptr, nullptr, nullptr, p_sr, Dd, Bq, Dd, 2*Dd);
    k_row_norm<<<Bq, 128>>>(p_sr, p_sr);

    // ---- Stage G: logits + log_softmax ----
    gemm(p_sr, Dd, emb, Dd, 1, nullptr, p_sc, nullptr, out, Vv, Bq, Vv, Dd);
    k_lse<<<Bq, 256>>>(out, p_lse);
    k_sub<<<dim3((Vv+255)/256, Bq), 256>>>(out, p_lse);

    #undef ZERO
}

// round 6
// speedup vs baseline: 2.6444x; 1.4093x over previous
#include <cuda_runtime.h>
#include <math.h>
#include <stdint.h>

// Problem constants
#define Bq   512
#define NPGc 50
#define EPGc 60
#define Dd   128
#define Vv   100000
#define NSPLITS 4
#define NSCALE 12.0f
#define NN   (Bq*NPGc)   // 25600 nodes
#define EE   (Bq*EPGc)   // 30720 edges
#define ND   (NN*Dd)

// ---------------- scratch (device globals) ----------------------------------
__device__ float g_feat[ND];
__device__ float g_agg[3*ND];      // aggx | aggh | aggrh (also num1|num2)
__device__ float g_nv[4*NN];       // den1 | den2 | deg | dis
__device__ float g_gi[NN*384];     // gi / Gx
__device__ float g_gh[NN*384];     // gh / Gh
__device__ float g_x[ND];
__device__ float g_h[ND];
__device__ float g_t1[ND];
__device__ float g_t2[ND];
__device__ float g_rh[ND];
__device__ float g_zz[ND];
__device__ float g_emf[EE];
__device__ float g_tend[1];
__device__ float g_sc[Vv];
__device__ float g_q[Bq*Dd];
__device__ float g_cc[Bq*2*Dd];
__device__ float g_sr[Bq*Dd];
__device__ float g_wcx[128*384];   // [Wxr|Wxz|Wxh]
__device__ float g_wch[128*256];   // [Whr|Whz]
__device__ float g_bcx[384];
__device__ float g_bch[256];
__device__ float g_wc1[128*384];   // W1 @ gw_ih[:, :128].T
__device__ float g_wc2[128*384];   // W2 @ gw_ih[:, 128:].T

// ---------------- helpers ----------------------------------------------------
__global__ void k_zero2(float* p1, int n1, float* p2, int n2){
    int i = blockIdx.x*256 + threadIdx.x;
    if (i < n1) p1[i] = 0.f;
    else if (i - n1 < n2) p2[i - n1] = 0.f;
}

__global__ void k_gather_norm(const float* __restrict__ emb, const int* __restrict__ iid,
                              float* __restrict__ out){
    int n = blockIdx.x, d = threadIdx.x;
    float v = emb[(size_t)iid[n]*Dd + d];
    float s = v*v;
    #pragma unroll
    for (int o = 16; o; o >>= 1) s += __shfl_xor_sync(0xffffffffu, s, o);
    __shared__ float sh[4];
    if ((d & 31) == 0) sh[d>>5] = s;
    __syncthreads();
    float tot = sh[0]+sh[1]+sh[2]+sh[3];
    out[(size_t)n*Dd + d] = v / fmaxf(sqrtf(tot), 1e-12f);
}

__global__ void k_row_norm(const float* __restrict__ in, float* __restrict__ out){
    int n = blockIdx.x, d = threadIdx.x;
    float v = in[(size_t)n*Dd + d];
    float s = v*v;
    #pragma unroll
    for (int o = 16; o; o >>= 1) s += __shfl_xor_sync(0xffffffffu, s, o);
    __shared__ float sh[4];
    if ((d & 31) == 0) sh[d>>5] = s;
    __syncthreads();
    float tot = sh[0]+sh[1]+sh[2]+sh[3];
    out[(size_t)n*Dd + d] = v / fmaxf(sqrtf(tot), 1e-12f);
}

__global__ void k_emb_scale(const float* __restrict__ emb, float* __restrict__ sc){
    int v = blockIdx.x, d = threadIdx.x;
    float x = emb[(size_t)v*Dd + d];
    float s = x*x;
    #pragma unroll
    for (int o = 16; o; o >>= 1) s += __shfl_xor_sync(0xffffffffu, s, o);
    __shared__ float sh[4];
    if ((d & 31) == 0) sh[d>>5] = s;
    __syncthreads();
    if (d == 0){
        float tot = sh[0]+sh[1]+sh[2]+sh[3];
        sc[v] = NSCALE / fmaxf(sqrtf(tot), 1e-12f);
    }
}

__global__ void k_den(const int* __restrict__ src, const int* __restrict__ dst,
                      const float* __restrict__ w, float* den1, float* den2){
    int e = blockIdx.x*256 + threadIdx.x;
    if (e >= EE) return;
    float ww = w[e];
    atomicAdd(&den1[dst[e]], ww);
    atomicAdd(&den2[src[e]], ww);
}

__global__ void k_recip(float* d, int n){
    int i = blockIdx.x*256 + threadIdx.x;
    if (i >= n) return;
    float v = d[i];
    d[i] = (v == 0.f) ? 1.f : 1.f/v;
}

__global__ void k_segnum(const int* __restrict__ src, const int* __restrict__ dst,
                         const float* __restrict__ w, const float* __restrict__ feat,
                         float* num1, float* num2){
    int e = blockIdx.x, d = threadIdx.x;
    int s = src[e], t = dst[e];
    float ww = w[e];
    atomicAdd(&num1[(size_t)t*Dd + d], feat[(size_t)s*Dd + d]*ww);
    atomicAdd(&num2[(size_t)s*Dd + d], feat[(size_t)t*Dd + d]*ww);
}

// pack ODE conv weights + biases once
__global__ void k_pack(const float* Wxr, const float* Wxz, const float* Wxh,
                       const float* Whr, const float* Whz,
                       const float* bxr, const float* bxz, const float* bxh,
                       const float* bhr, const float* bhz,
                       float* Wcx, float* Wch, float* bcx, float* bch){
    int i = blockIdx.x*256 + threadIdx.x;
    if (i < 49152){
        int k = i / 384, j = i % 384;
        const float* W = (j < 128) ? Wxr : ((j < 256) ? Wxz : Wxh);
        Wcx[i] = W[k*128 + (j & 127)];
    } else if (i < 81920){
        int t = i - 49152;
        int k = t / 256, j = t % 256;
        const float* W = (j < 128) ? Whr : Whz;
        Wch[t] = W[k*128 + (j & 127)];
    } else if (i < 82304){
        int j = i - 81920;
        bcx[j] = (j < 128) ? bxr[j] : ((j < 256) ? bxz[j-128] : bxh[j-256]);
    } else if (i < 82560){
        int j = i - 82304;
        bch[j] = (j < 128) ? bhr[j] : bhz[j-128];
    }
}

// ---------------- TF32 tensor-core GEMM with cp.async double buffering -------
// C[n,m] (+= if accum) = rowscale[n] * (sum_k A[n,k]*B(k,m)) * colscale[m] + bias[m]
__device__ __forceinline__ void cp16(uint32_t dst, const float* src, bool pred){
    int sz = pred ? 16 : 0;
    asm volatile("cp.async.cg.shared.global [%0], [%1], 16, %2;"
                 :: "r"(dst), "l"(src), "r"(sz));
}

__global__ __launch_bounds__(256)
void k_gemm_tc(const float* __restrict__ A, int lda,
               const float* __restrict__ Bm, int ldb, int transB,
               const float* __restrict__ bias,
               const float* __restrict__ colscale,
               const float* __restrict__ rowscale,
               float* __restrict__ C, int ldc,
               int Nr, int Mc, int K, int accum)
{
    __shared__ float sA[2][2560];   // [m 0..127][k 0..15], stride 20
    __shared__ float sB[2][2560];   // transB: [n][k] stride 20; else [k][m] stride 136
    int brow = blockIdx.x*128;
    int bcol = blockIdx.y*128;
    int tid  = threadIdx.x;
    int warp = tid >> 5, lane = tid & 31;
    int gid  = lane >> 2, tig = lane & 3;
    int wm   = (warp & 3) * 32;
    int wn   = (warp >> 2) * 64;

    float acc[2][8][4];
    #pragma unroll
    for (int mt = 0; mt < 2; mt++)
        #pragma unroll
        for (int nt = 0; nt < 8; nt++)
            #pragma unroll
            for (int f = 0; f < 4; f++) acc[mt][nt][f] = 0.f;

    int nk = K >> 4;

    // ---- staging lambda-ish macros ----
    #define STAGE(st, k0) do {                                                  \
        uint32_t sa = (uint32_t)__cvta_generic_to_shared(&sA[st][0]);           \
        uint32_t sb = (uint32_t)__cvta_generic_to_shared(&sB[st][0]);           \
        int c = tid;                                                            \
        _Pragma("unroll")                                                       \
        for (int j = 0; j < 2; j++, c += 256){                                  \
            int row = c >> 2, ko = (c & 3) * 4;                                 \
            int gr = brow + row;                                                \
            cp16(sa + (uint32_t)(row*20 + ko)*4,                                \
                 A + (size_t)gr*lda + (k0) + ko, gr < Nr);                      \
        }                                                                       \
        c = tid;                                                                \
        if (transB){                                                            \
            _Pragma("unroll")                                                   \
            for (int j = 0; j < 2; j++, c += 256){                              \
                int row = c >> 2, ko = (c & 3) * 4;                             \
                int gm = bcol + row;                                            \
                cp16(sb + (uint32_t)(row*20 + ko)*4,                            \
                     Bm + (size_t)gm*ldb + (k0) + ko, gm < Mc);                 \
            }                                                                   \
        } else {                                                                \
            _Pragma("unroll")                                                   \
            for (int j = 0; j < 2; j++, c += 256){                              \
                int kr = c >> 5, mo = (c & 31) * 4;                             \
                int gm = bcol + mo;                                             \
                cp16(sb + (uint32_t)(kr*136 + mo)*4,                            \
                     Bm + (size_t)((k0) + kr)*ldb + gm, gm < Mc);               \
            }                                                                   \
        }                                                                       \
    } while(0)

    STAGE(0, 0);
    asm volatile("cp.async.commit_group;");

    for (int kc = 0; kc < nk; kc++){
        if (kc + 1 < nk){ STAGE((kc+1)&1, (kc+1)*16); }
        asm volatile("cp.async.commit_group;");
        asm volatile("cp.async.wait_group 1;");
        __syncthreads();

        const float* sa = sA[kc & 1];
        const float* sb = sB[kc & 1];
        #pragma unroll
        for (int ks = 0; ks < 16; ks += 8){
            uint32_t a[2][4], b[8][2];
            #pragma unroll
            for (int mt = 0; mt < 2; mt++){
                int rb = wm + mt*16;
                a[mt][0] = __float_as_uint(sa[(rb+gid  )*20 + ks+tig  ]);
                a[mt][1] = __float_as_uint(sa[(rb+gid+8)*20 + ks+tig  ]);
                a[mt][2] = __float_as_uint(sa[(rb+gid  )*20 + ks+tig+4]);
                a[mt][3] = __float_as_uint(sa[(rb+gid+8)*20 + ks+tig+4]);
            }
            #pragma unroll
            for (int nt = 0; nt < 8; nt++){
                int cb = wn + nt*8;
                if (transB){
                    b[nt][0] = __float_as_uint(sb[(cb+gid)*20 + ks+tig  ]);
                    b[nt][1] = __float_as_uint(sb[(cb+gid)*20 + ks+tig+4]);
                } else {
                    b[nt][0] = __float_as_uint(sb[(ks+tig  )*136 + cb+gid]);
                    b[nt][1] = __float_as_uint(sb[(ks+tig+4)*136 + cb+gid]);
                }
            }
            #pragma unroll
            for (int mt = 0; mt < 2; mt++)
                #pragma unroll
                for (int nt = 0; nt < 8; nt++)
                    asm volatile(
                        "mma.sync.aligned.m16n8k8.row.col.f32.tf32.tf32.f32 "
                        "{%0,%1,%2,%3}, {%4,%5,%6,%7}, {%8,%9}, {%0,%1,%2,%3};"
                        : "+f"(acc[mt][nt][0]), "+f"(acc[mt][nt][1]),
                          "+f"(acc[mt][nt][2]), "+f"(acc[mt][nt][3])
                        : "r"(a[mt][0]), "r"(a[mt][1]), "r"(a[mt][2]), "r"(a[mt][3]),
                          "r"(b[nt][0]), "r"(b[nt][1]));
        }
        __syncthreads();
    }
    #undef STAGE

    #pragma unroll
    for (int mt = 0; mt < 2; mt++){
        #pragma unroll
        for (int half = 0; half < 2; half++){
            int r = brow + wm + mt*16 + gid + half*8;
            if (r >= Nr) continue;
            float rs = rowscale ? rowscale[r] : 1.f;
            #pragma unroll
            for (int nt = 0; nt < 8; nt++){
                int c0 = bcol + wn + nt*8 + tig*2;
                #pragma unroll
                for (int jj = 0; jj < 2; jj++){
                    int cm = c0 + jj;
                    if (cm >= Mc) continue;
                    float v = acc[mt][nt][half*2 + jj] * rs;
                    if (colscale) v *= colscale[cm];
                    if (bias) v += bias[cm];
                    if (accum) v += C[(size_t)r*ldc + cm];
                    C[(size_t)r*ldc + cm] = v;
                }
            }
        }
    }
}

// ---------------- fused GRU + l2norm + copy to x,h ---------------------------
__global__ void k_gru_norm(const float* __restrict__ gi, const float* __restrict__ gh,
                           float* __restrict__ feat, float* __restrict__ x,
                           float* __restrict__ h){
    int n = blockIdx.x, d = threadIdx.x;
    size_t b3 = (size_t)n*384 + d;
    float ir = gi[b3], iz = gi[b3+128], ig = gi[b3+256];
    float hr = gh[b3], hz = gh[b3+128], hg = gh[b3+256];
    float r = 1.f/(1.f + expf(-(ir + hr)));
    float z = 1.f/(1.f + expf(-(iz + hz)));
    float g = tanhf(ig + r*hg);
    size_t i = (size_t)n*Dd + d;
    float f = (1.f - z)*g + z*feat[i];
    float s = f*f;
    #pragma unroll
    for (int o = 16; o; o >>= 1) s += __shfl_xor_sync(0xffffffffu, s, o);
    __shared__ float sh[4];
    if ((d & 31) == 0) sh[d>>5] = s;
    __syncthreads();
    float tot = sh[0]+sh[1]+sh[2]+sh[3];
    float nf = f / fmaxf(sqrtf(tot), 1e-12f);
    feat[i] = nf; x[i] = nf; h[i] = nf;
}

// ---------------- ODE machinery ----------------------------------------------
__global__ void k_tmax(const float* __restrict__ et, float* tend){
    int i = blockIdx.x*256 + threadIdx.x;
    float v = (i < EE) ? et[i] : 0.f;
    #pragma unroll
    for (int o = 16; o; o >>= 1) v = fmaxf(v, __shfl_xor_sync(0xffffffffu, v, o));
    if ((threadIdx.x & 31) == 0) atomicMax((int*)tend, __float_as_int(v));
}

__global__ void k_mask(const float* __restrict__ edge_t, const float* __restrict__ node_t,
                       const int* __restrict__ src, const int* __restrict__ dst,
                       const float* __restrict__ tend, int kstep,
                       float* __restrict__ emf, float* deg){
    int e = blockIdx.x*256 + threadIdx.x;
    if (e >= EE) return;
    float dt = tend[0] / (float)NSPLITS;
    float t = (float)kstep * dt;
    int s = src[e], d = dst[e];
    float m = (edge_t[e] <= t && node_t[s] >= t && node_t[d] >= t && s != d) ? 1.f : 0.f;
    emf[e] = m;
    if (m > 0.f){ atomicAdd(&deg[s], 1.f); atomicAdd(&deg[d], 1.f); }
}

__global__ void k_dis(const float* __restrict__ deg, float* __restrict__ dis){
    int n = blockIdx.x*256 + threadIdx.x;
    if (n < NN) dis[n] = 1.f / sqrtf(fmaxf(deg[n], 1.f));
}

// dual aggregate: x and h through the same masked edges
__global__ void k_agg2(const int* __restrict__ src, const int* __restrict__ dst,
                       const float* __restrict__ emf, const float* __restrict__ dis,
                       const float* __restrict__ x, const float* __restrict__ h,
                       float* aggx, float* aggh){
    int e = blockIdx.x, d = threadIdx.x;
    if (emf[e] == 0.f) return;
    int s = src[e], t = dst[e];
    float ds = dis[s], dt_ = dis[t];
    atomicAdd(&aggx[(size_t)t*Dd + d], x[(size_t)s*Dd + d]*ds);
    atomicAdd(&aggx[(size_t)s*Dd + d], x[(size_t)t*Dd + d]*dt_);
    atomicAdd(&aggh[(size_t)t*Dd + d], h[(size_t)s*Dd + d]*ds);
    atomicAdd(&aggh[(size_t)s*Dd + d], h[(size_t)t*Dd + d]*dt_);
}

__global__ void k_agg1(const int* __restrict__ src, const int* __restrict__ dst,
                       const float* __restrict__ emf, const float* __restrict__ dis,
                       const float* __restrict__ inp, float* agg){
    int e = blockIdx.x, d = threadIdx.x;
    if (emf[e] == 0.f) return;
    int s = src[e], t = dst[e];
    atomicAdd(&agg[(size_t)t*Dd + d], inp[(size_t)s*Dd + d]*dis[s]);
    atomicAdd(&agg[(size_t)s*Dd + d], inp[(size_t)t*Dd + d]*dis[t]);
}

// rr,zz from Gx/Gh; also rh = rr*h
__global__ void k_rz(const float* __restrict__ Gx, const float* __restrict__ Gh,
                     const float* __restrict__ h, float* __restrict__ zz,
                     float* __restrict__ rh){
    int i = blockIdx.x*256 + threadIdx.x;
    if (i >= ND) return;
    int n = i >> 7, d = i & 127;
    size_t bx = (size_t)n*384 + d, bh = (size_t)n*256 + d;
    float rr = 1.f/(1.f + expf(-(Gx[bx]     + Gh[bh]    )));
    float zv = 1.f/(1.f + expf(-(Gx[bx+128] + Gh[bh+128])));
    zz[i] = zv;
    rh[i] = rr * h[i];
}

// uu = tanh(Gx[:,256:384] + t2); h += dt * mask * (1-zz)*(uu-h)
__global__ void k_upd(const float* __restrict__ Gx, const float* __restrict__ t2,
                      const float* __restrict__ zz, const float* __restrict__ node_t,
                      const float* __restrict__ tend, int kstep, float* __restrict__ h){
    int i = blockIdx.x*256 + threadIdx.x;
    if (i >= ND) return;
    int n = i >> 7, d = i & 127;
    float uu = tanhf(Gx[(size_t)n*384 + 256 + d] + t2[i]);
    float dt = tend[0] / (float)NSPLITS;
    float t = (float)kstep * dt;
    float hv = h[i];
    float dh = (node_t[n] >= t) ? (1.f - zz[i])*(uu - hv) : 0.f;
    h[i] = hv + dt*dh;
}

// ---------------- attention readout ------------------------------------------
__global__ void k_attn(const float* __restrict__ feat, const float* __restrict__ q,
                       const float* __restrict__ fwu, const float* __restrict__ We,
                       float* __restrict__ cc){
    int b = blockIdx.x, d = threadIdx.x;
    __shared__ float e_sh[NPGc];
    __shared__ float red[4];
    const float* fb  = feat + (size_t)b*NPGc*Dd;
    const float* fwb = fwu  + (size_t)b*NPGc*Dd;
    float qd = q[(size_t)b*Dd + d];
    float wed = We[d];
    for (int i = 0; i < NPGc; i++){
        float s = (1.f/(1.f + expf(-(fwb[(size_t)i*Dd + d] + qd)))) * wed;
        #pragma unroll
        for (int o = 16; o; o >>= 1) s += __shfl_xor_sync(0xffffffffu, s, o);
        if ((d & 31) == 0) red[d>>5] = s;
        __syncthreads();
        if (d == 0) e_sh[i] = red[0]+red[1]+red[2]+red[3];
        __syncthreads();
    }
    float mx = -1e30f;
    for (int i = 0; i < NPGc; i++) mx = fmaxf(mx, e_sh[i]);
    float sm = 0.f;
    for (int i = 0; i < NPGc; i++) sm += expf(e_sh[i] - mx);
    float srg = 0.f;
    for (int i = 0; i < NPGc; i++) srg += fb[(size_t)i*Dd + d]*(expf(e_sh[i] - mx)/sm);
    cc[(size_t)b*2*Dd + d]      = fb[(size_t)(NPGc-1)*Dd + d];
    cc[(size_t)b*2*Dd + Dd + d] = srg;
}

// ---------------- fused log-softmax (lse + subtract in one kernel) -----------
__global__ void k_logsoftmax(float* __restrict__ out){
    int b = blockIdx.x, t = threadIdx.x;   // 256 threads
    float* row = out + (size_t)b*Vv;
    __shared__ float sh[256];
    float mx = -1e30f;
    for (int v = t; v < Vv; v += 256) mx = fmaxf(mx, row[v]);
    sh[t] = mx; __syncthreads();
    for (int o = 128; o; o >>= 1){ if (t < o) sh[t] = fmaxf(sh[t], sh[t+o]); __syncthreads(); }
    mx = sh[0]; __syncthreads();
    float s = 0.f;
    for (int v = t; v < Vv; v += 256) s += expf(row[v] - mx);
    sh[t] = s; __syncthreads();
    for (int o = 128; o; o >>= 1){ if (t < o) sh[t] += sh[t+o]; __syncthreads(); }
    float lse = mx + logf(sh[0]);
    for (int v = t; v < Vv; v += 256) row[v] -= lse;
}

// ---------------- host orchestration -----------------------------------------
static inline void gemm(const float* A, int lda, const float* B, int ldb, int tB,
                        const float* bias, const float* cs, const float* rs,
                        float* C, int ldc, int Nr, int Mc, int K, int accum = 0){
    dim3 grid((Nr + 127)/128, (Mc + 127)/128);
    k_gemm_tc<<<grid, 256>>>(A, lda, B, ldb, tB, bias, cs, rs, C, ldc, Nr, Mc, K, accum);
}

extern "C" void kernel_launch(void* const* d_in, const int* in_sizes, int n_in,
                              void* d_out, int out_size)
{
    const int*   iid    = (const int*)  d_in[0];
    const int*   src    = (const int*)  d_in[1];
    const int*   dst    = (const int*)  d_in[2];
    const float* edge_w = (const float*)d_in[3];
    const float* edge_t = (const float*)d_in[4];
    const float* node_t = (const float*)d_in[5];
    const float* emb    = (const float*)d_in[6];
    const float* W1     = (const float*)d_in[7];
    const float* W2     = (const float*)d_in[8];
    const float* gw_ih  = (const float*)d_in[9];
    const float* gw_hh  = (const float*)d_in[10];
    const float* gb_ih  = (const float*)d_in[11];
    const float* gb_hh  = (const float*)d_in[12];
    const float* Wxr = (const float*)d_in[13]; const float* bxr = (const float*)d_in[14];
    const float* Wxz = (const float*)d_in[15]; const float* bxz = (const float*)d_in[16];
    const float* Wxh = (const float*)d_in[17]; const float* bxh = (const float*)d_in[18];
    const float* Whr = (const float*)d_in[19]; const float* bhr = (const float*)d_in[20];
    const float* Whz = (const float*)d_in[21]; const float* bhz = (const float*)d_in[22];
    const float* Whh = (const float*)d_in[23]; const float* bhh = (const float*)d_in[24];
    const float* Wu  = (const float*)d_in[25];
    const float* Wv  = (const float*)d_in[26];
    const float* bv  = (const float*)d_in[27];
    const float* We  = (const float*)d_in[28];
    const float* W_sr= (const float*)d_in[29];
    float* out = (float*)d_out;

    float *p_feat,*p_agg,*p_nv,*p_gi,*p_gh,*p_x,*p_h,*p_t1,*p_t2,*p_rh,*p_zz;
    float *p_emf,*p_tend,*p_sc,*p_q,*p_cc,*p_sr;
    float *p_wcx,*p_wch,*p_bcx,*p_bch,*p_wc1,*p_wc2;
    cudaGetSymbolAddress((void**)&p_feat, g_feat);
    cudaGetSymbolAddress((void**)&p_agg,  g_agg);
    cudaGetSymbolAddress((void**)&p_nv,   g_nv);
    cudaGetSymbolAddress((void**)&p_gi,   g_gi);
    cudaGetSymbolAddress((void**)&p_gh,   g_gh);
    cudaGetSymbolAddress((void**)&p_x,    g_x);
    cudaGetSymbolAddress((void**)&p_h,    g_h);
    cudaGetSymbolAddress((void**)&p_t1,   g_t1);
    cudaGetSymbolAddress((void**)&p_t2,   g_t2);
    cudaGetSymbolAddress((void**)&p_rh,   g_rh);
    cudaGetSymbolAddress((void**)&p_zz,   g_zz);
    cudaGetSymbolAddress((void**)&p_emf,  g_emf);
    cudaGetSymbolAddress((void**)&p_tend, g_tend);
    cudaGetSymbolAddress((void**)&p_sc,   g_sc);
    cudaGetSymbolAddress((void**)&p_q,    g_q);
    cudaGetSymbolAddress((void**)&p_cc,   g_cc);
    cudaGetSymbolAddress((void**)&p_sr,   g_sr);
    cudaGetSymbolAddress((void**)&p_wcx,  g_wcx);
    cudaGetSymbolAddress((void**)&p_wch,  g_wch);
    cudaGetSymbolAddress((void**)&p_bcx,  g_bcx);
    cudaGetSymbolAddress((void**)&p_bch,  g_bch);
    cudaGetSymbolAddress((void**)&p_wc1,  g_wc1);
    cudaGetSymbolAddress((void**)&p_wc2,  g_wc2);

    float* p_aggx  = p_agg;
    float* p_aggh  = p_agg + ND;
    float* p_aggrh = p_agg + 2*ND;
    float* p_den1  = p_nv;
    float* p_den2  = p_nv + NN;
    float* p_deg   = p_nv + 2*NN;
    float* p_dis   = p_nv + 3*NN;

    // ---- Stage A + weight prep ----
    k_gather_norm<<<NN, 128>>>(emb, iid, p_feat);
    k_emb_scale<<<Vv, 128>>>(emb, p_sc);
    k_pack<<<(82560+255)/256, 256>>>(Wxr, Wxz, Wxh, Whr, Whz,
                                     bxr, bxz, bxh, bhr, bhz,
                                     p_wcx, p_wch, p_bcx, p_bch);
    // Wc1 = W1 @ gw_ih[:, :128].T ; Wc2 = W2 @ gw_ih[:, 128:].T  (both 128x384)
    gemm(W1, 128, gw_ih,       256, 1, nullptr, nullptr, nullptr, p_wc1, 384, 128, 384, 128);
    gemm(W2, 128, gw_ih + 128, 256, 1, nullptr, nullptr, nullptr, p_wc2, 384, 128, 384, 128);

    // ---- Stage B: weighted neighbor sums ----
    k_zero2<<<(2*ND + 2*NN + 255)/256, 256>>>(p_agg, 2*ND, p_nv, 2*NN);
    k_den<<<(EE+255)/256, 256>>>(src, dst, edge_w, p_den1, p_den2);
    k_segnum<<<EE, 128>>>(src, dst, edge_w, p_feat, p_aggx, p_aggh);
    k_recip<<<(2*NN+255)/256, 256>>>(p_nv, 2*NN);

    // ---- Stage C: gi = num1@Wc1 + num2@Wc2 + gb_ih ; gh = feat@gw_hh.T + gb_hh
    gemm(p_aggx, Dd, p_wc1, 384, 0, gb_ih,  nullptr, p_den1, p_gi, 384, NN, 384, Dd, 0);
    gemm(p_aggh, Dd, p_wc2, 384, 0, nullptr, nullptr, p_den2, p_gi, 384, NN, 384, Dd, 1);
    gemm(p_feat, Dd, gw_hh, Dd, 1, gb_hh,  nullptr, nullptr, p_gh, 384, NN, 384, Dd, 0);

    // ---- Stage D: fused GRU + norm + copy to x,h ----
    k_gru_norm<<<NN, 128>>>(p_gi, p_gh, p_feat, p_x, p_h);

    // ---- Stage E: ODE ----
    k_zero2<<<1, 256>>>(p_tend, 1, p_tend, 0);
    k_tmax<<<(EE+255)/256, 256>>>(edge_t, p_tend);

    for (int k = 0; k < NSPLITS; k++){
        k_zero2<<<(3*ND + NN + 255)/256, 256>>>(p_agg, 3*ND, p_deg, NN);
        k_mask<<<(EE+255)/256, 256>>>(edge_t, node_t, src, dst, p_tend, k, p_emf, p_deg);
        k_dis<<<(NN+255)/256, 256>>>(p_deg, p_dis);
        k_agg2<<<EE, 128>>>(src, dst, p_emf, p_dis, p_x, p_h, p_aggx, p_aggh);
        gemm(p_aggx, Dd, p_wcx, 384, 0, p_bcx, nullptr, p_dis, p_gi, 384, NN, 384, Dd, 0); // Gx
        gemm(p_aggh, Dd, p_wch, 256, 0, p_bch, nullptr, p_dis, p_gh, 256, NN, 256, Dd, 0); // Gh
        k_rz<<<(ND+255)/256, 256>>>(p_gi, p_gh, p_h, p_zz, p_rh);
        k_agg1<<<EE, 128>>>(src, dst, p_emf, p_dis, p_rh, p_aggrh);
        gemm(p_aggrh, Dd, Whh, Dd, 0, bhh, nullptr, p_dis, p_t2, Dd, NN, Dd, Dd, 0);
        k_upd<<<(ND+255)/256, 256>>>(p_gi, p_t2, p_zz, node_t, p_tend, k, p_h);
    }
    k_row_norm<<<NN, 128>>>(p_h, p_feat);

    // ---- Stage F: attention readout ----
    gemm(p_feat, Dd, Wu, Dd, 0, nullptr, nullptr, nullptr, p_t1, Dd, NN, Dd, Dd, 0);
    gemm(p_feat + (NPGc-1)*Dd, NPGc*Dd, Wv, Dd, 0, bv, nullptr, nullptr, p_q, Dd, Bq, Dd, Dd, 0);
    k_attn<<<Bq, 128>>>(p_feat, p_q, p_t1, We, p_cc);
    gemm(p_cc, 2*Dd, W_sr, Dd, 0, nullptr, nullptr, nullptr, p_sr, Dd, Bq, Dd, 2*Dd, 0);
    k_row_norm<<<Bq, 128>>>(p_sr, p_sr);

    // ---- Stage G: logits + log_softmax ----
    gemm(p_sr, Dd, emb, Dd, 1, nullptr, p_sc, nullptr, out, Vv, Bq, Vv, Dd, 0);
    k_logsoftmax<<<Bq, 256>>>(out);
}

// round 10
// speedup vs baseline: 2.7550x; 1.0418x over previous
#include <cuda_runtime.h>
#include <cuda_fp16.h>
#include <math.h>
#include <stdint.h>

// Problem constants
#define Bq   512
#define NPGc 50
#define EPGc 60
#define Dd   128
#define Vv   100000
#define NSPLITS 4
#define NSCALE 12.0f
#define NN   (Bq*NPGc)   // 25600 nodes
#define EE   (Bq*EPGc)   // 30720 edges
#define ND   (NN*Dd)

// ---------------- scratch (device globals) ----------------------------------
__device__ float g_feat[ND];
__device__ float g_agg[3*ND];      // aggx | aggh | aggrh (also num1|num2)
__device__ float g_nv[4*NN];       // den1 | den2 | deg | dis
__device__ float g_gi[NN*384];     // gi / Gx
__device__ float g_gh[NN*384];     // gh / Gh
__device__ float g_x[ND];
__device__ float g_h[ND];
__device__ float g_t1[ND];
__device__ float g_t2[ND];
__device__ float g_rh[ND];
__device__ float g_zz[ND];
__device__ float g_emf[EE];
__device__ float g_tend[1];
__device__ float g_sc[Vv];
__device__ float g_q[Bq*Dd];
__device__ float g_cc[Bq*2*Dd];
__device__ float g_sr[Bq*Dd];
// fp16 mirrors -------------------------------------------------------------
__device__ __half g_agg16[3*ND];
__device__ __half g_feat16[ND];
__device__ __half g_cc16[Bq*2*Dd];
__device__ __half g_sr16[Bq*Dd];
__device__ __half g_emb16[(size_t)Vv*Dd];
__device__ __half g_gwih16[384*256];
__device__ __half g_w116[128*128];
__device__ __half g_w216[128*128];
__device__ __half g_gwhh16[384*128];
// transposed packed weights (rows = output cols, K-major)
__device__ __half g_wcxT16[384*128];  // [Wxr|Wxz|Wxh]^T
__device__ __half g_wchT16[256*128];  // [Whr|Whz]^T
__device__ __half g_whhT16[128*128];
__device__ __half g_wuT16 [128*128];
__device__ __half g_wvT16 [128*128];
__device__ __half g_wsrT16[128*256];
__device__ __half g_wc1T16[384*128];
__device__ __half g_wc2T16[384*128];
__device__ float g_bcx[384];
__device__ float g_bch[256];

// ---------------- fp16 tensor-core GEMM --------------------------------------
// C[r, n] (+= if accum) = rowscale[r]*(sum_k A[r,k]*B[n,k])*colscale[n] + bias[n]
// A: [Nr, K] halves (lda). B: [Mc, K] halves (ldb) — B rows are output columns.
// CTA tile 128x128, BK=32, 256 threads (8 warps 4x2), warp tile 32x64,
// mma.sync.m16n8k16 f16 with f32 accumulate, cp.async double buffering.
__device__ __forceinline__ void cph16(uint32_t dst, const __half* src, bool pred){
    int sz = pred ? 16 : 0;
    asm volatile("cp.async.cg.shared.global [%0], [%1], 16, %2;"
                 :: "r"(dst), "l"(src), "r"(sz));
}

__global__ __launch_bounds__(256)
void k_gemm_h(const __half* __restrict__ A, int lda,
              const __half* __restrict__ Bm, int ldb,
              const float* __restrict__ bias,
              const float* __restrict__ colscale,
              const float* __restrict__ rowscale,
              float* __restrict__ C, int ldc,
              int Nr, int Mc, int K, int accum)
{
    __shared__ __half sA[2][128*40];   // [row][k], row stride 40 halves (80B)
    __shared__ __half sB[2][128*40];
    int brow = blockIdx.x*128;
    int bcol = blockIdx.y*128;
    int tid  = threadIdx.x;
    int warp = tid >> 5, lane = tid & 31;
    int gid  = lane >> 2, tig = lane & 3;
    int wm   = (warp & 3) * 32;
    int wn   = (warp >> 2) * 64;

    float acc[2][8][4];
    #pragma unroll
    for (int mt = 0; mt < 2; mt++)
        #pragma unroll
        for (int nt = 0; nt < 8; nt++)
            #pragma unroll
            for (int f = 0; f < 4; f++) acc[mt][nt][f] = 0.f;

    int nchunk = K >> 5;

    // stage one 128x32-half chunk of A and B into buffer st, global k offset gk0
    // (lambda — proper scoping; the round-9 macro version had a variable-shadow
    //  bug where the inner k-sub-chunk index shadowed the outer loop variable
    //  referenced by the textual macro argument)
    auto stage = [&](int st, int gk0){
        uint32_t sa = (uint32_t)__cvta_generic_to_shared(&sA[st][0]);
        uint32_t sb = (uint32_t)__cvta_generic_to_shared(&sB[st][0]);
        #pragma unroll
        for (int j = 0; j < 2; j++){
            int c   = tid + j*256;
            int row = c >> 2;
            int kq  = c & 3;                 // 16-byte sub-chunk within the row
            int gr  = brow + row;
            cph16(sa + (uint32_t)(row*80 + kq*16),
                  A + (size_t)gr*lda + gk0 + kq*8, gr < Nr);
        }
        #pragma unroll
        for (int j = 0; j < 2; j++){
            int c   = tid + j*256;
            int row = c >> 2;
            int kq  = c & 3;
            int gm  = bcol + row;
            cph16(sb + (uint32_t)(row*80 + kq*16),
                  Bm + (size_t)gm*ldb + gk0 + kq*8, gm < Mc);
        }
    };

    stage(0, 0);
    asm volatile("cp.async.commit_group;");

    for (int kc = 0; kc < nchunk; kc++){
        if (kc + 1 < nchunk){ stage((kc+1)&1, (kc+1)*32); }
        asm volatile("cp.async.commit_group;");
        asm volatile("cp.async.wait_group 1;");
        __syncthreads();

        const __half* sa = sA[kc & 1];
        const __half* sb = sB[kc & 1];
        #pragma unroll
        for (int ks = 0; ks < 32; ks += 16){
            uint32_t a[2][4], b[8][2];
            #pragma unroll
            for (int mt = 0; mt < 2; mt++){
                int rb = wm + mt*16;
                a[mt][0] = *(const uint32_t*)&sa[(rb+gid  )*40 + ks + 2*tig    ];
                a[mt][1] = *(const uint32_t*)&sa[(rb+gid+8)*40 + ks + 2*tig    ];
                a[mt][2] = *(const uint32_t*)&sa[(rb+gid  )*40 + ks + 2*tig + 8];
                a[mt][3] = *(const uint32_t*)&sa[(rb+gid+8)*40 + ks + 2*tig + 8];
            }
            #pragma unroll
            for (int nt = 0; nt < 8; nt++){
                int cb = wn + nt*8;
                b[nt][0] = *(const uint32_t*)&sb[(cb+gid)*40 + ks + 2*tig    ];
                b[nt][1] = *(const uint32_t*)&sb[(cb+gid)*40 + ks + 2*tig + 8];
            }
            #pragma unroll
            for (int mt = 0; mt < 2; mt++)
                #pragma unroll
                for (int nt = 0; nt < 8; nt++)
                    asm volatile(
                        "mma.sync.aligned.m16n8k16.row.col.f32.f16.f16.f32 "
                        "{%0,%1,%2,%3}, {%4,%5,%6,%7}, {%8,%9}, {%0,%1,%2,%3};"
                        : "+f"(acc[mt][nt][0]), "+f"(acc[mt][nt][1]),
                          "+f"(acc[mt][nt][2]), "+f"(acc[mt][nt][3])
                        : "r"(a[mt][0]), "r"(a[mt][1]), "r"(a[mt][2]), "r"(a[mt][3]),
                          "r"(b[nt][0]), "r"(b[nt][1]));
        }
        __syncthreads();
    }

    // epilogue: c0:(gid,2tig) c1:(gid,2tig+1) c2:(gid+8,2tig) c3:(gid+8,2tig+1)
    #pragma unroll
    for (int mt = 0; mt < 2; mt++){
        #pragma unroll
        for (int half = 0; half < 2; half++){
            int r = brow + wm + mt*16 + gid + half*8;
            if (r >= Nr) continue;
            float rs = rowscale ? rowscale[r] : 1.f;
            #pragma unroll
            for (int nt = 0; nt < 8; nt++){
                int c0 = bcol + wn + nt*8 + tig*2;
                #pragma unroll
                for (int jj = 0; jj < 2; jj++){
                    int cm = c0 + jj;
                    if (cm >= Mc) continue;
                    float v = acc[mt][nt][half*2 + jj] * rs;
                    if (colscale) v *= colscale[cm];
                    if (bias) v += bias[cm];
                    if (accum) v += C[(size_t)r*ldc + cm];
                    C[(size_t)r*ldc + cm] = v;
                }
            }
        }
    }
}

// ---------------- conversions -------------------------------------------------
__global__ void k_cvt(const float* __restrict__ in, __half* __restrict__ out, int n4){
    int i = blockIdx.x*256 + threadIdx.x;
    if (i >= n4) return;
    float4 v = ((const float4*)in)[i];
    ((__half2*)out)[2*i]   = __floats2half2_rn(v.x, v.y);
    ((__half2*)out)[2*i+1] = __floats2half2_rn(v.z, v.w);
}

// ---------------- helpers -----------------------------------------------------
__global__ void k_zero2(float* p1, int n1, float* p2, int n2){
    int i = blockIdx.x*256 + threadIdx.x;
    if (i < n1) p1[i] = 0.f;
    else if (i - n1 < n2) p2[i - n1] = 0.f;
}

__global__ void k_gather_norm(const float* __restrict__ emb, const int* __restrict__ iid,
                              float* __restrict__ out, __half* __restrict__ out16){
    int n = blockIdx.x, d = threadIdx.x;
    float v = emb[(size_t)iid[n]*Dd + d];
    float s = v*v;
    #pragma unroll
    for (int o = 16; o; o >>= 1) s += __shfl_xor_sync(0xffffffffu, s, o);
    __shared__ float sh[4];
    if ((d & 31) == 0) sh[d>>5] = s;
    __syncthreads();
    float tot = sh[0]+sh[1]+sh[2]+sh[3];
    float nf = v / fmaxf(sqrtf(tot), 1e-12f);
    out[(size_t)n*Dd + d] = nf;
    out16[(size_t)n*Dd + d] = __float2half_rn(nf);
}

// row l2norm writing f32 + optional half
__global__ void k_row_norm_h(const float* __restrict__ in, float* __restrict__ out,
                             __half* __restrict__ out16){
    int n = blockIdx.x, d = threadIdx.x;
    float v = in[(size_t)n*Dd + d];
    float s = v*v;
    #pragma unroll
    for (int o = 16; o; o >>= 1) s += __shfl_xor_sync(0xffffffffu, s, o);
    __shared__ float sh[4];
    if ((d & 31) == 0) sh[d>>5] = s;
    __syncthreads();
    float tot = sh[0]+sh[1]+sh[2]+sh[3];
    float nf = v / fmaxf(sqrtf(tot), 1e-12f);
    out[(size_t)n*Dd + d] = nf;
    if (out16) out16[(size_t)n*Dd + d] = __float2half_rn(nf);
}

__global__ void k_emb_scale(const float* __restrict__ emb, float* __restrict__ sc){
    int v = blockIdx.x, d = threadIdx.x;
    float x = emb[(size_t)v*Dd + d];
    float s = x*x;
    #pragma unroll
    for (int o = 16; o; o >>= 1) s += __shfl_xor_sync(0xffffffffu, s, o);
    __shared__ float sh[4];
    if ((d & 31) == 0) sh[d>>5] = s;
    __syncthreads();
    if (d == 0){
        float tot = sh[0]+sh[1]+sh[2]+sh[3];
        sc[v] = NSCALE / fmaxf(sqrtf(tot), 1e-12f);
    }
}

__global__ void k_den(const int* __restrict__ src, const int* __restrict__ dst,
                      const float* __restrict__ w, float* den1, float* den2){
    int e = blockIdx.x*256 + threadIdx.x;
    if (e >= EE) return;
    float ww = w[e];
    atomicAdd(&den1[dst[e]], ww);
    atomicAdd(&den2[src[e]], ww);
}

__global__ void k_recip(float* d, int n){
    int i = blockIdx.x*256 + threadIdx.x;
    if (i >= n) return;
    float v = d[i];
    d[i] = (v == 0.f) ? 1.f : 1.f/v;
}

__global__ void k_segnum(const int* __restrict__ src, const int* __restrict__ dst,
                         const float* __restrict__ w, const float* __restrict__ feat,
                         float* num1, float* num2){
    int e = blockIdx.x, d = threadIdx.x;
    int s = src[e], t = dst[e];
    float ww = w[e];
    atomicAdd(&num1[(size_t)t*Dd + d], feat[(size_t)s*Dd + d]*ww);
    atomicAdd(&num2[(size_t)s*Dd + d], feat[(size_t)t*Dd + d]*ww);
}

// pack transposed half weights + f32 biases
__global__ void k_pack(const float* Wxr, const float* Wxz, const float* Wxh,
                       const float* Whr, const float* Whz, const float* Whh,
                       const float* Wu, const float* Wv, const float* W_sr,
                       const float* bxr, const float* bxz, const float* bxh,
                       const float* bhr, const float* bhz,
                       __half* WcxT, __half* WchT, __half* WhhT,
                       __half* WuT, __half* WvT, __half* WsrT,
                       float* bcx, float* bch){
    int i = blockIdx.x*256 + threadIdx.x;
    if (i < 49152){                       // WcxT [384,128]
        int j = i >> 7, k = i & 127;
        const float* W = (j < 128) ? Wxr : ((j < 256) ? Wxz : Wxh);
        WcxT[i] = __float2half_rn(W[k*128 + (j & 127)]);
    } else if (i < 81920){                // WchT [256,128]
        int t = i - 49152;
        int j = t >> 7, k = t & 127;
        const float* W = (j < 128) ? Whr : Whz;
        WchT[t] = __float2half_rn(W[k*128 + (j & 127)]);
    } else if (i < 98304){                // WhhT
        int t = i - 81920;
        int j = t >> 7, k = t & 127;
        WhhT[t] = __float2half_rn(Whh[k*128 + j]);
    } else if (i < 114688){               // WuT
        int t = i - 98304;
        int j = t >> 7, k = t & 127;
        WuT[t] = __float2half_rn(Wu[k*128 + j]);
    } else if (i < 131072){               // WvT
        int t = i - 114688;
        int j = t >> 7, k = t & 127;
        WvT[t] = __float2half_rn(Wv[k*128 + j]);
    } else if (i < 163840){               // WsrT [128,256]
        int t = i - 131072;
        int j = t >> 8, k = t & 255;
        WsrT[t] = __float2half_rn(W_sr[k*128 + j]);
    } else if (i < 164224){               // bcx
        int j = i - 163840;
        bcx[j] = (j < 128) ? bxr[j] : ((j < 256) ? bxz[j-128] : bxh[j-256]);
    } else if (i < 164480){               // bch
        int j = i - 164224;
        bch[j] = (j < 128) ? bhr[j] : bhz[j-128];
    }
}

// ---------------- fused GRU + l2norm + copy to x,h ----------------------------
__global__ void k_gru_norm(const float* __restrict__ gi, const float* __restrict__ gh,
                           float* __restrict__ feat, float* __restrict__ x,
                           float* __restrict__ h){
    int n = blockIdx.x, d = threadIdx.x;
    size_t b3 = (size_t)n*384 + d;
    float ir = gi[b3], iz = gi[b3+128], ig = gi[b3+256];
    float hr = gh[b3], hz = gh[b3+128], hg = gh[b3+256];
    float r = 1.f/(1.f + expf(-(ir + hr)));
    float z = 1.f/(1.f + expf(-(iz + hz)));
    float g = tanhf(ig + r*hg);
    size_t i = (size_t)n*Dd + d;
    float f = (1.f - z)*g + z*feat[i];
    float s = f*f;
    #pragma unroll
    for (int o = 16; o; o >>= 1) s += __shfl_xor_sync(0xffffffffu, s, o);
    __shared__ float sh[4];
    if ((d & 31) == 0) sh[d>>5] = s;
    __syncthreads();
    float tot = sh[0]+sh[1]+sh[2]+sh[3];
    float nf = f / fmaxf(sqrtf(tot), 1e-12f);
    feat[i] = nf; x[i] = nf; h[i] = nf;
}

// ---------------- ODE machinery -----------------------------------------------
__global__ void k_tmax(const float* __restrict__ et, float* tend){
    int i = blockIdx.x*256 + threadIdx.x;
    float v = (i < EE) ? et[i] : 0.f;
    #pragma unroll
    for (int o = 16; o; o >>= 1) v = fmaxf(v, __shfl_xor_sync(0xffffffffu, v, o));
    if ((threadIdx.x & 31) == 0) atomicMax((int*)tend, __float_as_int(v));
}

__global__ void k_mask(const float* __restrict__ edge_t, const float* __restrict__ node_t,
                       const int* __restrict__ src, const int* __restrict__ dst,
                       const float* __restrict__ tend, int kstep,
                       float* __restrict__ emf, float* deg){
    int e = blockIdx.x*256 + threadIdx.x;
    if (e >= EE) return;
    float dt = tend[0] / (float)NSPLITS;
    float t = (float)kstep * dt;
    int s = src[e], d = dst[e];
    float m = (edge_t[e] <= t && node_t[s] >= t && node_t[d] >= t && s != d) ? 1.f : 0.f;
    emf[e] = m;
    if (m > 0.f){ atomicAdd(&deg[s], 1.f); atomicAdd(&deg[d], 1.f); }
}

__global__ void k_dis(const float* __restrict__ deg, float* __restrict__ dis){
    int n = blockIdx.x*256 + threadIdx.x;
    if (n < NN) dis[n] = 1.f / sqrtf(fmaxf(deg[n], 1.f));
}

__global__ void k_agg2(const int* __restrict__ src, const int* __restrict__ dst,
                       const float* __restrict__ emf, const float* __restrict__ dis,
                       const float* __restrict__ x, const float* __restrict__ h,
                       float* aggx, float* aggh){
    int e = blockIdx.x, d = threadIdx.x;
    if (emf[e] == 0.f) return;
    int s = src[e], t = dst[e];
    float ds = dis[s], dt_ = dis[t];
    atomicAdd(&aggx[(size_t)t*Dd + d], x[(size_t)s*Dd + d]*ds);
    atomicAdd(&aggx[(size_t)s*Dd + d], x[(size_t)t*Dd + d]*dt_);
    atomicAdd(&aggh[(size_t)t*Dd + d], h[(size_t)s*Dd + d]*ds);
    atomicAdd(&aggh[(size_t)s*Dd + d], h[(size_t)t*Dd + d]*dt_);
}

__global__ void k_agg1(const int* __restrict__ src, const int* __restrict__ dst,
                       const float* __restrict__ emf, const float* __restrict__ dis,
                       const float* __restrict__ inp, float* agg){
    int e = blockIdx.x, d = threadIdx.x;
    if (emf[e] == 0.f) return;
    int s = src[e], t = dst[e];
    atomicAdd(&agg[(size_t)t*Dd + d], inp[(size_t)s*Dd + d]*dis[s]);
    atomicAdd(&agg[(size_t)s*Dd + d], inp[(size_t)t*Dd + d]*dis[t]);
}

__global__ void k_rz(const float* __restrict__ Gx, const float* __restrict__ Gh,
                     const float* __restrict__ h, float* __restrict__ zz,
                     float* __restrict__ rh){
    int i = blockIdx.x*256 + threadIdx.x;
    if (i >= ND) return;
    int n = i >> 7, d = i & 127;
    size_t bx = (size_t)n*384 + d, bh = (size_t)n*256 + d;
    float rr = 1.f/(1.f + expf(-(Gx[bx]     + Gh[bh]    )));
    float zv = 1.f/(1.f + expf(-(Gx[bx+128] + Gh[bh+128])));
    zz[i] = zv;
    rh[i] = rr * h[i];
}

__global__ void k_upd(const float* __restrict__ Gx, const float* __restrict__ t2,
                      const float* __restrict__ zz, const float* __restrict__ node_t,
                      const float* __restrict__ tend, int kstep, float* __restrict__ h){
    int i = blockIdx.x*256 + threadIdx.x;
    if (i >= ND) return;
    int n = i >> 7, d = i & 127;
    float uu = tanhf(Gx[(size_t)n*384 + 256 + d] + t2[i]);
    float dt = tend[0] / (float)NSPLITS;
    float t = (float)kstep * dt;
    float hv = h[i];
    float dh = (node_t[n] >= t) ? (1.f - zz[i])*(uu - hv) : 0.f;
    h[i] = hv + dt*dh;
}

// ---------------- attention readout -------------------------------------------
__global__ void k_attn(const float* __restrict__ feat, const float* __restrict__ q,
                       const float* __restrict__ fwu, const float* __restrict__ We,
                       float* __restrict__ cc){
    int b = blockIdx.x, d = threadIdx.x;
    __shared__ float e_sh[NPGc];
    __shared__ float red[4];
    const float* fb  = feat + (size_t)b*NPGc*Dd;
    const float* fwb = fwu  + (size_t)b*NPGc*Dd;
    float qd = q[(size_t)b*Dd + d];
    float wed = We[d];
    for (int i = 0; i < NPGc; i++){
        float s = (1.f/(1.f + expf(-(fwb[(size_t)i*Dd + d] + qd)))) * wed;
        #pragma unroll
        for (int o = 16; o; o >>= 1) s += __shfl_xor_sync(0xffffffffu, s, o);
        if ((d & 31) == 0) red[d>>5] = s;
        __syncthreads();
        if (d == 0) e_sh[i] = red[0]+red[1]+red[2]+red[3];
        __syncthreads();
    }
    float mx = -1e30f;
    for (int i = 0; i < NPGc; i++) mx = fmaxf(mx, e_sh[i]);
    float sm = 0.f;
    for (int i = 0; i < NPGc; i++) sm += expf(e_sh[i] - mx);
    float srg = 0.f;
    for (int i = 0; i < NPGc; i++) srg += fb[(size_t)i*Dd + d]*(expf(e_sh[i] - mx)/sm);
    cc[(size_t)b*2*Dd + d]      = fb[(size_t)(NPGc-1)*Dd + d];
    cc[(size_t)b*2*Dd + Dd + d] = srg;
}

// ---------------- fused log-softmax -------------------------------------------
__global__ void k_logsoftmax(float* __restrict__ out){
    int b = blockIdx.x, t = threadIdx.x;   // 256 threads
    float* row = out + (size_t)b*Vv;
    __shared__ float sh[256];
    float mx = -1e30f;
    for (int v = t; v < Vv; v += 256) mx = fmaxf(mx, row[v]);
    sh[t] = mx; __syncthreads();
    for (int o = 128; o; o >>= 1){ if (t < o) sh[t] = fmaxf(sh[t], sh[t+o]); __syncthreads(); }
    mx = sh[0]; __syncthreads();
    float s = 0.f;
    for (int v = t; v < Vv; v += 256) s += expf(row[v] - mx);
    sh[t] = s; __syncthreads();
    for (int o = 128; o; o >>= 1){ if (t < o) sh[t] += sh[t+o]; __syncthreads(); }
    float lse = mx + logf(sh[0]);
    for (int v = t; v < Vv; v += 256) row[v] -= lse;
}

// ---------------- host orchestration ------------------------------------------
static inline void gemm(const __half* A, int lda, const __half* B, int ldb,
                        const float* bias, const float* cs, const float* rs,
                        float* C, int ldc, int Nr, int Mc, int K, int accum = 0){
    dim3 grid((Nr + 127)/128, (Mc + 127)/128);
    k_gemm_h<<<grid, 256>>>(A, lda, B, ldb, bias, cs, rs, C, ldc, Nr, Mc, K, accum);
}

extern "C" void kernel_launch(void* const* d_in, const int* in_sizes, int n_in,
                              void* d_out, int out_size)
{
    const int*   iid    = (const int*)  d_in[0];
    const int*   src    = (const int*)  d_in[1];
    const int*   dst    = (const int*)  d_in[2];
    const float* edge_w = (const float*)d_in[3];
    const float* edge_t = (const float*)d_in[4];
    const float* node_t = (const float*)d_in[5];
    const float* emb    = (const float*)d_in[6];
    const float* W1     = (const float*)d_in[7];
    const float* W2     = (const float*)d_in[8];
    const float* gw_ih  = (const float*)d_in[9];
    const float* gw_hh  = (const float*)d_in[10];
    const float* gb_ih  = (const float*)d_in[11];
    const float* gb_hh  = (const float*)d_in[12];
    const float* Wxr = (const float*)d_in[13]; const float* bxr = (const float*)d_in[14];
    const float* Wxz = (const float*)d_in[15]; const float* bxz = (const float*)d_in[16];
    const float* Wxh = (const float*)d_in[17]; const float* bxh = (const float*)d_in[18];
    const float* Whr = (const float*)d_in[19]; const float* bhr = (const float*)d_in[20];
    const float* Whz = (const float*)d_in[21]; const float* bhz = (const float*)d_in[22];
    const float* Whh = (const float*)d_in[23]; const float* bhh = (const float*)d_in[24];
    const float* Wu  = (const float*)d_in[25];
    const float* Wv  = (const float*)d_in[26];
    const float* bv  = (const float*)d_in[27];
    const float* We  = (const float*)d_in[28];
    const float* W_sr= (const float*)d_in[29];
    float* out = (float*)d_out;

    float *p_feat,*p_agg,*p_nv,*p_gi,*p_gh,*p_x,*p_h,*p_t1,*p_t2,*p_rh,*p_zz;
    float *p_emf,*p_tend,*p_sc,*p_q,*p_cc,*p_sr,*p_bcx,*p_bch;
    __half *p_agg16,*p_feat16,*p_cc16,*p_sr16,*p_emb16,*p_gwih16,*p_w116,*p_w216;
    __half *p_gwhh16,*p_wcxT16,*p_wchT16,*p_whhT16,*p_wuT16,*p_wvT16,*p_wsrT16;
    __half *p_wc1T16,*p_wc2T16;
    cudaGetSymbolAddress((void**)&p_feat, g_feat);
    cudaGetSymbolAddress((void**)&p_agg,  g_agg);
    cudaGetSymbolAddress((void**)&p_nv,   g_nv);
    cudaGetSymbolAddress((void**)&p_gi,   g_gi);
    cudaGetSymbolAddress((void**)&p_gh,   g_gh);
    cudaGetSymbolAddress((void**)&p_x,    g_x);
    cudaGetSymbolAddress((void**)&p_h,    g_h);
    cudaGetSymbolAddress((void**)&p_t1,   g_t1);
    cudaGetSymbolAddress((void**)&p_t2,   g_t2);
    cudaGetSymbolAddress((void**)&p_rh,   g_rh);
    cudaGetSymbolAddress((void**)&p_zz,   g_zz);
    cudaGetSymbolAddress((void**)&p_emf,  g_emf);
    cudaGetSymbolAddress((void**)&p_tend, g_tend);
    cudaGetSymbolAddress((void**)&p_sc,   g_sc);
    cudaGetSymbolAddress((void**)&p_q,    g_q);
    cudaGetSymbolAddress((void**)&p_cc,   g_cc);
    cudaGetSymbolAddress((void**)&p_sr,   g_sr);
    cudaGetSymbolAddress((void**)&p_bcx,  g_bcx);
    cudaGetSymbolAddress((void**)&p_bch,  g_bch);
    cudaGetSymbolAddress((void**)&p_agg16, g_agg16);
    cudaGetSymbolAddress((void**)&p_feat16,g_feat16);
    cudaGetSymbolAddress((void**)&p_cc16, g_cc16);
    cudaGetSymbolAddress((void**)&p_sr16, g_sr16);
    cudaGetSymbolAddress((void**)&p_emb16,g_emb16);
    cudaGetSymbolAddress((void**)&p_gwih16,g_gwih16);
    cudaGetSymbolAddress((void**)&p_w116, g_w116);
    cudaGetSymbolAddress((void**)&p_w216, g_w216);
    cudaGetSymbolAddress((void**)&p_gwhh16,g_gwhh16);
    cudaGetSymbolAddress((void**)&p_wcxT16,g_wcxT16);
    cudaGetSymbolAddress((void**)&p_wchT16,g_wchT16);
    cudaGetSymbolAddress((void**)&p_whhT16,g_whhT16);
    cudaGetSymbolAddress((void**)&p_wuT16, g_wuT16);
    cudaGetSymbolAddress((void**)&p_wvT16, g_wvT16);
    cudaGetSymbolAddress((void**)&p_wsrT16,g_wsrT16);
    cudaGetSymbolAddress((void**)&p_wc1T16,g_wc1T16);
    cudaGetSymbolAddress((void**)&p_wc2T16,g_wc2T16);

    float*  p_aggx   = p_agg;
    float*  p_aggh   = p_agg + ND;
    float*  p_aggrh  = p_agg + 2*ND;
    __half* p_aggx16 = p_agg16;
    __half* p_aggh16 = p_agg16 + ND;
    __half* p_aggrh16= p_agg16 + 2*ND;
    float* p_den1  = p_nv;
    float* p_den2  = p_nv + NN;
    float* p_deg   = p_nv + 2*NN;
    float* p_dis   = p_nv + 3*NN;

    #define CVT(src, dst, n) k_cvt<<<((n)/4 + 255)/256, 256>>>(src, dst, (n)/4)

    // ---- Stage A + weight prep ----
    k_gather_norm<<<NN, 128>>>(emb, iid, p_feat, p_feat16);
    k_emb_scale<<<Vv, 128>>>(emb, p_sc);
    CVT(emb,   p_emb16,  Vv*Dd);
    CVT(gw_ih, p_gwih16, 384*256);
    CVT(W1,    p_w116,   128*128);
    CVT(W2,    p_w216,   128*128);
    CVT(gw_hh, p_gwhh16, 384*128);
    k_pack<<<(164480+255)/256, 256>>>(Wxr, Wxz, Wxh, Whr, Whz, Whh, Wu, Wv, W_sr,
                                      bxr, bxz, bxh, bhr, bhz,
                                      p_wcxT16, p_wchT16, p_whhT16, p_wuT16, p_wvT16,
                                      p_wsrT16, p_bcx, p_bch);
    // Wc1T[j,k] = sum_c gw_ih[j,c]*W1[k,c]  (transB-native)
    gemm(p_gwih16,       256, p_w116, 128, nullptr, nullptr, nullptr, p_t1, 128, 384, 128, 128);
    gemm(p_gwih16 + 128, 256, p_w216, 128, nullptr, nullptr, nullptr, p_t2, 128, 384, 128, 128);
    CVT(p_t1, p_wc1T16, 384*128);
    CVT(p_t2, p_wc2T16, 384*128);

    // ---- Stage B: weighted neighbor sums ----
    k_zero2<<<(2*ND + 2*NN + 255)/256, 256>>>(p_agg, 2*ND, p_nv, 2*NN);
    k_den<<<(EE+255)/256, 256>>>(src, dst, edge_w, p_den1, p_den2);
    k_segnum<<<EE, 128>>>(src, dst, edge_w, p_feat, p_aggx, p_aggh);
    k_recip<<<(2*NN+255)/256, 256>>>(p_nv, 2*NN);
    CVT(p_agg, p_agg16, 2*ND);

    // ---- Stage C: gi = num1@Wc1 + num2@Wc2 + gb_ih ; gh = feat@gw_hh.T + gb_hh ----
    gemm(p_aggx16, Dd, p_wc1T16, 128, gb_ih,  nullptr, p_den1, p_gi, 384, NN, 384, Dd, 0);
    gemm(p_aggh16, Dd, p_wc2T16, 128, nullptr, nullptr, p_den2, p_gi, 384, NN, 384, Dd, 1);
    gemm(p_feat16, Dd, p_gwhh16, 128, gb_hh,  nullptr, nullptr, p_gh, 384, NN, 384, Dd, 0);

    // ---- Stage D: fused GRU + norm + copy to x,h ----
    k_gru_norm<<<NN, 128>>>(p_gi, p_gh, p_feat, p_x, p_h);

    // ---- Stage E: ODE ----
    k_zero2<<<1, 256>>>(p_tend, 1, p_tend, 0);
    k_tmax<<<(EE+255)/256, 256>>>(edge_t, p_tend);

    for (int k = 0; k < NSPLITS; k++){
        k_zero2<<<(3*ND + NN + 255)/256, 256>>>(p_agg, 3*ND, p_deg, NN);
        k_mask<<<(EE+255)/256, 256>>>(edge_t, node_t, src, dst, p_tend, k, p_emf, p_deg);
        k_dis<<<(NN+255)/256, 256>>>(p_deg, p_dis);
        k_agg2<<<EE, 128>>>(src, dst, p_emf, p_dis, p_x, p_h, p_aggx, p_aggh);
        CVT(p_agg, p_agg16, 2*ND);
        gemm(p_aggx16, Dd, p_wcxT16, 128, p_bcx, nullptr, p_dis, p_gi, 384, NN, 384, Dd, 0);
        gemm(p_aggh16, Dd, p_wchT16, 128, p_bch, nullptr, p_dis, p_gh, 256, NN, 256, Dd, 0);
        k_rz<<<(ND+255)/256, 256>>>(p_gi, p_gh, p_h, p_zz, p_rh);
        k_agg1<<<EE, 128>>>(src, dst, p_emf, p_dis, p_rh, p_aggrh);
        CVT(p_aggrh, p_aggrh16, ND);
        gemm(p_aggrh16, Dd, p_whhT16, 128, bhh, nullptr, p_dis, p_t2, Dd, NN, Dd, Dd, 0);
        k_upd<<<(ND+255)/256, 256>>>(p_gi, p_t2, p_zz, node_t, p_tend, k, p_h);
    }
    k_row_norm_h<<<NN, 128>>>(p_h, p_feat, p_feat16);

    // ---- Stage F: attention readout ----
    gemm(p_feat16, Dd, p_wuT16, 128, nullptr, nullptr, nullptr, p_t1, Dd, NN, Dd, Dd, 0);
    gemm(p_feat16 + (size_t)(NPGc-1)*Dd, NPGc*Dd, p_wvT16, 128, bv, nullptr, nullptr,
         p_q, Dd, Bq, Dd, Dd, 0);
    k_attn<<<Bq, 128>>>(p_feat, p_q, p_t1, We, p_cc);
    CVT(p_cc, p_cc16, Bq*2*Dd);
    gemm(p_cc16, 2*Dd, p_wsrT16, 256, nullptr, nullptr, nullptr, p_sr, Dd, Bq, Dd, 2*Dd, 0);
    k_row_norm_h<<<Bq, 128>>>(p_sr, p_sr, p_sr16);

    // ---- Stage G: logits + log_softmax ----
    gemm(p_sr16, Dd, p_emb16, 128, nullptr, p_sc, nullptr, out, Vv, Bq, Vv, Dd, 0);
    k_logsoftmax<<<Bq, 256>>>(out);

    #undef CVT
}